// round 11
// baseline (speedup 1.0000x reference)
#include <cuda_runtime.h>

#define BB 8
#define CC 64
#define NP 16384
#define RR 32
#define NV 32768          // 32^3
#define ALPHA 0.1f
#define BNEPS 1e-4f
#define VOXEPS 1e-6f

// ---------------- scratch (device globals; no allocation allowed) ----------
__device__ float g_fT[BB * NP * CC];        // features transposed [b][n][c]
__device__ float g_tmp[BB * NV * CC];       // voxel sums [b][v][c]; later raw conv2 out
__device__ float g_cnt[BB * NV];            // voxel counts
__device__ float g_bufB[BB * CC * NV];      // conv1 output (channels-last [b][v][c])
__device__ float g_pT[BB * NP * CC];        // point branch [b][n][c]
__device__ float g_normc[BB * 3 * NP];      // normalized coords in [0,31]
__device__ float g_cmean[BB * 3];           // coordinate SUMS
__device__ unsigned g_cmaxb[BB];            // max dist^2 as float bits
__device__ float g_stats[6 * CC];           // sum1,sq1,sum2,sq2,psum,psq
__device__ float g_scsh[6 * CC];            // sc1,sh1,sc2,sh2,scp,shp

// ---------------- utility kernels ----------------
__global__ void zero_kernel(float* p, size_t n) {
    size_t i = (size_t)blockIdx.x * blockDim.x + threadIdx.x;
    size_t stride = (size_t)gridDim.x * blockDim.x;
    for (; i < n; i += stride) p[i] = 0.0f;
}

__global__ void zero_small(float* stats, float* cmean, unsigned* cmaxb) {
    int t = threadIdx.x;
    if (t < 6 * CC) stats[t] = 0.0f;
    if (t < BB * 3) cmean[t] = 0.0f;
    if (t < BB) cmaxb[t] = 0u;
}

__global__ void copy_kernel(const float* __restrict__ src, float* __restrict__ dst, int n) {
    int i = blockIdx.x * blockDim.x + threadIdx.x;
    int stride = gridDim.x * blockDim.x;
    for (; i < n; i += stride) dst[i] = src[i];
}

__global__ void mkscale(const float* __restrict__ sum, const float* __restrict__ sumsq,
                        const float* __restrict__ gamma, const float* __restrict__ beta,
                        float invcnt, float* __restrict__ sc, float* __restrict__ sh) {
    int c = threadIdx.x;
    float mean = sum[c] * invcnt;
    float var = sumsq[c] * invcnt - mean * mean;
    float s = gamma[c] * rsqrtf(var + BNEPS);
    sc[c] = s;
    sh[c] = beta[c] - mean * s;
}

// ---------------- features transpose [b][c][n] -> [b][n][c] ----------------
__global__ void transpose_feat(const float* __restrict__ feat, float* __restrict__ fT) {
    __shared__ float s[CC][33];
    int b = blockIdx.y;
    int n0 = blockIdx.x * 32;
    int t = threadIdx.x;
    for (int i = t; i < 32 * 64; i += 256) {
        int c = i >> 5, n = i & 31;
        s[c][n] = feat[(b * CC + c) * NP + n0 + n];
    }
    __syncthreads();
    for (int i = t; i < 32 * 64; i += 256) {
        int n = i >> 6, c = i & 63;
        fT[((size_t)b * NP + n0 + n) * CC + c] = s[c][n];
    }
}

// ---------------- coord statistics ----------------
__global__ void coord_mean_p(const float* __restrict__ coords, float* __restrict__ cmean) {
    int b = blockIdx.y;
    int n0 = blockIdx.x * 512;
    int t = threadIdx.x;
    float s0 = 0, s1 = 0, s2 = 0;
    for (int n = n0 + t; n < n0 + 512; n += 256) {
        s0 += coords[(b * 3 + 0) * NP + n];
        s1 += coords[(b * 3 + 1) * NP + n];
        s2 += coords[(b * 3 + 2) * NP + n];
    }
#pragma unroll
    for (int o = 16; o > 0; o >>= 1) {
        s0 += __shfl_xor_sync(0xffffffff, s0, o);
        s1 += __shfl_xor_sync(0xffffffff, s1, o);
        s2 += __shfl_xor_sync(0xffffffff, s2, o);
    }
    if ((t & 31) == 0) {
        atomicAdd(&cmean[b * 3 + 0], s0);
        atomicAdd(&cmean[b * 3 + 1], s1);
        atomicAdd(&cmean[b * 3 + 2], s2);
    }
}

__global__ void coord_max_p(const float* __restrict__ coords, const float* __restrict__ cmean,
                            unsigned* __restrict__ cmaxb) {
    int b = blockIdx.y;
    int n0 = blockIdx.x * 512;
    int t = threadIdx.x;
    float invn = 1.0f / (float)NP;
    float mx = cmean[b * 3 + 0] * invn, my = cmean[b * 3 + 1] * invn, mz = cmean[b * 3 + 2] * invn;
    float m = 0.0f;
    for (int n = n0 + t; n < n0 + 512; n += 256) {
        float dx = coords[(b * 3 + 0) * NP + n] - mx;
        float dy = coords[(b * 3 + 1) * NP + n] - my;
        float dz = coords[(b * 3 + 2) * NP + n] - mz;
        m = fmaxf(m, dx * dx + dy * dy + dz * dz);
    }
#pragma unroll
    for (int o = 16; o > 0; o >>= 1) m = fmaxf(m, __shfl_xor_sync(0xffffffff, m, o));
    if ((t & 31) == 0) atomicMax(&cmaxb[b], __float_as_uint(m));
}

// ---------------- voxelize scatter ----------------
__global__ void scatter(const float* __restrict__ coords, const float* __restrict__ fT,
                        const float* __restrict__ cmean, const unsigned* __restrict__ cmaxb,
                        float* __restrict__ normc, float* __restrict__ tmp,
                        float* __restrict__ cnt) {
    int t = threadIdx.x;
    int pi = blockIdx.x * 4 + (t >> 6);
    int c = t & 63;
    int b = pi / NP;
    int n = pi - b * NP;

    float invn = 1.0f / (float)NP;
    float r = sqrtf(__uint_as_float(cmaxb[b]));
    float inv = 1.0f / (2.0f * r + VOXEPS);
    float nx = (coords[(b * 3 + 0) * NP + n] - cmean[b * 3 + 0] * invn) * inv + 0.5f;
    float ny = (coords[(b * 3 + 1) * NP + n] - cmean[b * 3 + 1] * invn) * inv + 0.5f;
    float nz = (coords[(b * 3 + 2) * NP + n] - cmean[b * 3 + 2] * invn) * inv + 0.5f;
    nx = fminf(fmaxf(nx * (float)RR, 0.0f), (float)(RR - 1));
    ny = fminf(fmaxf(ny * (float)RR, 0.0f), (float)(RR - 1));
    nz = fminf(fmaxf(nz * (float)RR, 0.0f), (float)(RR - 1));
    int vx = __float2int_rn(nx), vy = __float2int_rn(ny), vz = __float2int_rn(nz);
    int v = (vx * RR + vy) * RR + vz;

    float f = fT[((size_t)b * NP + n) * CC + c];
    atomicAdd(&tmp[((size_t)b * NV + v) * CC + c], f);
    if (c == 0) atomicAdd(&cnt[b * NV + v], 1.0f);
    if (c < 3) normc[(b * 3 + c) * NP + n] = (c == 0 ? nx : (c == 1 ? ny : nz));
}

// ================= tf32 mma.sync conv =======================================
// CTA: M=128 spatial (4y x 32x) x N=64 cout, fixed (z,b). 8 warps, each 32x32.
// INMODE 0: input = voxel sums [b][v][c] / max(cnt,1)  (fuses finalize_vox)
// INMODE 2: input = channels-last [b][v][c] with BN+lrelu applied at load
// Output: channels-last [b][v][c] (raw conv + bias); fused BN stats.
// B' staging: fragment-ordered, stride 20 floats/slot -> 2x LDS.128 per K8.

static __device__ __forceinline__ float tf32_rna(float v) {
    unsigned u;
    asm("cvt.rna.tf32.f32 %0, %1;" : "=r"(u) : "f"(v));
    return __uint_as_float(u);
}

#define LDS32(dst, addr) asm volatile("ld.shared.b32 %0, [%1];" : "=r"(dst) : "r"(addr))
#define LDS128(r0, r1, r2, r3, addr)                                          \
    asm volatile("ld.shared.v4.b32 {%0,%1,%2,%3}, [%4];"                      \
                 : "=r"(r0), "=r"(r1), "=r"(r2), "=r"(r3) : "r"(addr))
#define MMA_TF32(d, a0, a1, a2, a3, b0, b1)                                   \
    asm volatile(                                                             \
        "mma.sync.aligned.m16n8k8.row.col.f32.tf32.tf32.f32 "                 \
        "{%0,%1,%2,%3}, {%4,%5,%6,%7}, {%8,%9}, {%0,%1,%2,%3};"               \
        : "+f"(d[0]), "+f"(d[1]), "+f"(d[2]), "+f"(d[3])                      \
        : "r"(a0), "r"(a1), "r"(a2), "r"(a3), "r"(b0), "r"(b1))

#define WSM_FLOATS 2560   // B': 4 ks x 32 slots x 20 floats
#define SLAB_FLOATS 22032 // (3z*6y)*34x rows x 36 pitch
#define RES_PITCH 68
#define CONV_DYN ((2 * WSM_FLOATS + SLAB_FLOATS) * 4)  // 108608 B

template <int INMODE>
__global__ __launch_bounds__(256, 2)
void conv3d_mma(const float* __restrict__ in, const float* __restrict__ cnt,
                float* __restrict__ out,
                const float* __restrict__ w, const float* __restrict__ bias,
                const float* __restrict__ insc, const float* __restrict__ insh,
                float* __restrict__ gsum, float* __restrict__ gsumsq) {
    extern __shared__ __align__(16) float dsm[];
    __shared__ float sc_sm[64], sh_sm[64], bias_sm[64];

    float* wsm0 = dsm;
    float* wsm1 = dsm + WSM_FLOATS;
    float* slab = dsm + 2 * WSM_FLOATS;
    float* res = slab;  // reused after compute (128 x RES_PITCH <= SLAB_FLOATS)

    int b = blockIdx.z, z0 = blockIdx.y, y0 = blockIdx.x * 4;
    int t = threadIdx.x, lane = t & 31, wid = t >> 5;
    int wy = wid >> 1, wn = wid & 1;
    int gid = lane >> 2, tig = lane & 3;

    unsigned slab_s = (unsigned)__cvta_generic_to_shared(slab);
    unsigned wsm_s[2] = {(unsigned)__cvta_generic_to_shared(wsm0),
                         (unsigned)__cvta_generic_to_shared(wsm1)};

    if (t < 64) {
        bias_sm[t] = bias[t];
        if (INMODE == 2) { sc_sm[t] = insc[t]; sh_sm[t] = insh[t]; }
    }
    __syncthreads();

    float acc[2][4][4];
#pragma unroll
    for (int mt = 0; mt < 2; mt++)
#pragma unroll
        for (int nt = 0; nt < 4; nt++)
#pragma unroll
            for (int e = 0; e < 4; e++) acc[mt][nt][e] = 0.0f;

    // channels-last slab: row (zs*6+ys)*34+xs, 32 channels, pitch 36 floats
    auto load_slab = [&](int cig) {
        for (int i = t; i < 4896; i += 256) {
            int zy = i / 272, r = i - zy * 272;
            int c4 = r / 34, xs = r - c4 * 34;
            int zs = zy / 6, ys = zy - zs * 6;
            int zg = z0 - 1 + zs, yg = y0 - 1 + ys, xg = xs - 1;
            bool ok = (unsigned)zg < 32u && (unsigned)yg < 32u && (unsigned)xg < 32u;
            int vox = zg * 1024 + yg * 32 + xg;
            float4 val;
            if (INMODE == 0) {
                float4 sums = ok ? __ldg((const float4*)(in + ((size_t)b * NV + vox) * CC
                                                          + cig * 32 + c4 * 4))
                                 : make_float4(0.f, 0.f, 0.f, 0.f);
                float inv = ok ? 1.0f / fmaxf(__ldg(cnt + (size_t)b * NV + vox), 1.0f) : 0.0f;
                val.x = tf32_rna(sums.x * inv);
                val.y = tf32_rna(sums.y * inv);
                val.z = tf32_rna(sums.z * inv);
                val.w = tf32_rna(sums.w * inv);
            } else {
                float4 v = ok ? __ldg((const float4*)(in + ((size_t)b * NV + vox) * CC
                                                       + cig * 32 + c4 * 4))
                              : make_float4(0.f, 0.f, 0.f, 0.f);
                int c = cig * 32 + c4 * 4;
                float u;
                u = fmaf(v.x, sc_sm[c + 0], sh_sm[c + 0]); v.x = u >= 0 ? u : ALPHA * u;
                u = fmaf(v.y, sc_sm[c + 1], sh_sm[c + 1]); v.y = u >= 0 ? u : ALPHA * u;
                u = fmaf(v.z, sc_sm[c + 2], sh_sm[c + 2]); v.z = u >= 0 ? u : ALPHA * u;
                u = fmaf(v.w, sc_sm[c + 3], sh_sm[c + 3]); v.w = u >= 0 ? u : ALPHA * u;
                if (!ok) v = make_float4(0.f, 0.f, 0.f, 0.f);  // pad AFTER transform
                val.x = tf32_rna(v.x); val.y = tf32_rna(v.y);
                val.z = tf32_rna(v.z); val.w = tf32_rna(v.w);
            }
            *(float4*)(slab + (size_t)((zs * 6 + ys) * 34 + xs) * 36 + c4 * 4) = val;
        }
    };

    float4 wr0, wr1;
    auto w_prefetch = [&](int cig, int koff) {
        const float4* wg = (const float4*)(w + (size_t)(koff * 64 + cig * 32) * 64);
        wr0 = __ldg(&wg[t]);
        wr1 = __ldg(&wg[t + 256]);
    };
    // B' layout: dest = ks*640 + (gid*4+tig)*20 + wn*8 + cihalf*4 + nt
    //   where ci = ks*8 + tig + cihalf*4, co = wn*32 + nt*8 + gid
    auto w_sts = [&](float* dst) {
#pragma unroll
        for (int k = 0; k < 2; k++) {
            float4 v = k ? wr1 : wr0;
            int e = (t + k * 256) * 4;             // element index in [ci*64+co]
            int ci = e >> 6, co = e & 63;          // co multiple of 4
            int ks = ci >> 3, r = ci & 7;
            int tg = r & 3, ch = r >> 2;
            int wnn = co >> 5, cc = co & 31;
            int nt = cc >> 3, gd0 = cc & 7;        // gd0 in {0,4}
            float* base = dst + ks * 640 + gd0 * 80 + tg * 20 + wnn * 8 + ch * 4 + nt;
            base[0]   = tf32_rna(v.x);
            base[80]  = tf32_rna(v.y);
            base[160] = tf32_rna(v.z);
            base[240] = tf32_rna(v.w);
        }
    };

    auto compute = [&](int buf, int koff) {
        int dz = koff / 9, rem = koff - dz * 9;
        int dy = rem / 3, dx = rem - dy * 3;
        unsigned a_base = slab_s +
            (unsigned)((((dz * 6 + wy + dy) * 34) + gid + dx) * 36 + tig) * 4;
        unsigned b_base = wsm_s[buf] + (unsigned)(lane * 20 + wn * 8) * 4;
#pragma unroll
        for (int ks = 0; ks < 4; ks++) {
            unsigned ab = a_base + ks * 32;
            unsigned bb = b_base + ks * 2560;      // 640 floats per ks
            unsigned a0, a1, a2, a3, a4, a5, a6, a7;
            LDS32(a0, ab);            LDS32(a1, ab + 1152);
            LDS32(a2, ab + 16);       LDS32(a3, ab + 1168);
            LDS32(a4, ab + 2304);     LDS32(a5, ab + 3456);
            LDS32(a6, ab + 2320);     LDS32(a7, ab + 3472);
            unsigned b0[4], b1[4];
            LDS128(b0[0], b0[1], b0[2], b0[3], bb);
            LDS128(b1[0], b1[1], b1[2], b1[3], bb + 16);
#pragma unroll
            for (int nt = 0; nt < 4; nt++) {
                MMA_TF32(acc[0][nt], a0, a1, a2, a3, b0[nt], b1[nt]);
                MMA_TF32(acc[1][nt], a4, a5, a6, a7, b0[nt], b1[nt]);
            }
        }
    };

#pragma unroll 1
    for (int cig = 0; cig < 2; cig++) {
        load_slab(cig);
        w_prefetch(cig, 0);
        w_sts(wsm0);
        __syncthreads();
#pragma unroll 1
        for (int koff = 0; koff < 27; koff++) {
            if (koff < 26) w_prefetch(cig, koff + 1);
            compute(koff & 1, koff);
            if (koff < 26) w_sts((koff & 1) ? wsm0 : wsm1);
            __syncthreads();
        }
    }

    // ---- epilogue: bounce D to smem; channels-last store + fused BN stats ----
#pragma unroll
    for (int mt = 0; mt < 2; mt++)
#pragma unroll
        for (int nt = 0; nt < 4; nt++) {
            int spat0 = wy * 32 + mt * 16 + gid;
            int cout0 = wn * 32 + nt * 8 + tig * 2;
            *(float2*)(res + spat0 * RES_PITCH + cout0) =
                make_float2(acc[mt][nt][0], acc[mt][nt][1]);
            *(float2*)(res + (spat0 + 8) * RES_PITCH + cout0) =
                make_float2(acc[mt][nt][2], acc[mt][nt][3]);
        }
    __syncthreads();

    {
        int s_ = t >> 1, h = t & 1;
        int vox = z0 * 1024 + (y0 + (s_ >> 5)) * 32 + (s_ & 31);
        float* op = out + ((size_t)b * NV + vox) * CC + h * 32;
        const float* rp = res + s_ * RES_PITCH + h * 32;
#pragma unroll
        for (int k = 0; k < 8; k++) {
            float4 v;
            v.x = rp[4 * k + 0] + bias_sm[h * 32 + 4 * k + 0];
            v.y = rp[4 * k + 1] + bias_sm[h * 32 + 4 * k + 1];
            v.z = rp[4 * k + 2] + bias_sm[h * 32 + 4 * k + 2];
            v.w = rp[4 * k + 3] + bias_sm[h * 32 + 4 * k + 3];
            *(float4*)(op + 4 * k) = v;
        }
    }
#pragma unroll
    for (int j = 0; j < 8; j++) {
        int c = wid * 8 + j;
        float bval = bias_sm[c];
        float s = 0, q = 0;
#pragma unroll
        for (int sy = 0; sy < 4; sy++) {
            float v = res[(sy * 32 + lane) * RES_PITCH + c] + bval;
            s += v; q += v * v;
        }
#pragma unroll
        for (int o = 16; o > 0; o >>= 1) {
            s += __shfl_xor_sync(0xffffffff, s, o);
            q += __shfl_xor_sync(0xffffffff, q, o);
        }
        if (lane == 0) { atomicAdd(&gsum[c], s); atomicAdd(&gsumsq[c], q); }
    }
}

// ================= tf32 mma.sync point GEMM + fused stats ===================
#define PGW_FLOATS 2304   // old scalar-B layout (32 ci x 72 pitch)
#define PG_A_FLOATS (2 * 128 * 36)    // 9216
#define PG_DYN ((PG_A_FLOATS + 2 * PGW_FLOATS) * 4)   // 55296 B

__global__ __launch_bounds__(256, 2)
void pgemm_mma(const float* __restrict__ fT, const float* __restrict__ w,
               const float* __restrict__ bias, float* __restrict__ pT,
               float* __restrict__ gsum, float* __restrict__ gsumsq) {
    extern __shared__ __align__(16) float dsm[];
    __shared__ float bias_sm[64];
    float* asm0 = dsm;                       // [cig][128][36]
    float* wsm0 = dsm + PG_A_FLOATS;         // [cig][32][72]
    float* res = dsm;                        // reuse after compute

    int b = blockIdx.y;
    int n0 = blockIdx.x * 128;
    int t = threadIdx.x, lane = t & 31, wid = t >> 5;
    int wy = wid >> 1, wn = wid & 1;
    int gid = lane >> 2, tig = lane & 3;

    unsigned a_s = (unsigned)__cvta_generic_to_shared(asm0);
    unsigned w_s = (unsigned)__cvta_generic_to_shared(wsm0);

    if (t < 64) bias_sm[t] = bias[t];

    for (int i = t; i < 2048; i += 256) {
        int n = i >> 4, c4 = i & 15;
        int cig = c4 >> 3, c4l = c4 & 7;
        float4 v = __ldg((const float4*)(fT + ((size_t)b * NP + n0 + n) * CC + c4 * 4));
        v.x = tf32_rna(v.x); v.y = tf32_rna(v.y);
        v.z = tf32_rna(v.z); v.w = tf32_rna(v.w);
        *(float4*)(asm0 + (size_t)cig * 128 * 36 + n * 36 + c4l * 4) = v;
    }
    {
        const float4* wg = (const float4*)w;
#pragma unroll
        for (int k = 0; k < 4; k++) {
            float4 v = __ldg(&wg[t + k * 256]);
            int e = (t + k * 256) * 4;
            int ci = e >> 6, co = e & 63;
            float* d = wsm0 + (size_t)(ci >> 5) * PGW_FLOATS + (ci & 31) * 72 + co;
            d[0] = tf32_rna(v.x); d[1] = tf32_rna(v.y);
            d[2] = tf32_rna(v.z); d[3] = tf32_rna(v.w);
        }
    }
    __syncthreads();

    float acc[2][4][4];
#pragma unroll
    for (int mt = 0; mt < 2; mt++)
#pragma unroll
        for (int nt = 0; nt < 4; nt++)
#pragma unroll
            for (int e = 0; e < 4; e++) acc[mt][nt][e] = 0.0f;

#pragma unroll
    for (int cig = 0; cig < 2; cig++) {
        unsigned a_base = a_s + (unsigned)(cig * 128 * 36 + (wy * 32 + gid) * 36 + tig) * 4;
        unsigned b_base = w_s + (unsigned)(cig * PGW_FLOATS + tig * 72 + wn * 32 + gid) * 4;
#pragma unroll
        for (int ks = 0; ks < 4; ks++) {
            unsigned ab = a_base + ks * 32;
            unsigned bb = b_base + ks * 2304;
            unsigned a0, a1, a2, a3, a4, a5, a6, a7;
            LDS32(a0, ab);            LDS32(a1, ab + 1152);
            LDS32(a2, ab + 16);       LDS32(a3, ab + 1168);
            LDS32(a4, ab + 2304);     LDS32(a5, ab + 3456);
            LDS32(a6, ab + 2320);     LDS32(a7, ab + 3472);
            unsigned b0[4], b1[4];
#pragma unroll
            for (int nt = 0; nt < 4; nt++) {
                LDS32(b0[nt], bb + nt * 32);
                LDS32(b1[nt], bb + nt * 32 + 1152);
            }
#pragma unroll
            for (int nt = 0; nt < 4; nt++) {
                MMA_TF32(acc[0][nt], a0, a1, a2, a3, b0[nt], b1[nt]);
                MMA_TF32(acc[1][nt], a4, a5, a6, a7, b0[nt], b1[nt]);
            }
        }
    }
    __syncthreads();

#pragma unroll
    for (int mt = 0; mt < 2; mt++)
#pragma unroll
        for (int nt = 0; nt < 4; nt++) {
            int spat0 = wy * 32 + mt * 16 + gid;
            int cout0 = wn * 32 + nt * 8 + tig * 2;
            *(float2*)(res + spat0 * RES_PITCH + cout0) =
                make_float2(acc[mt][nt][0], acc[mt][nt][1]);
            *(float2*)(res + (spat0 + 8) * RES_PITCH + cout0) =
                make_float2(acc[mt][nt][2], acc[mt][nt][3]);
        }
    __syncthreads();

    {
        int s_ = t >> 1, h = t & 1;
        float* op = pT + ((size_t)b * NP + n0 + s_) * CC + h * 32;
        const float* rp = res + s_ * RES_PITCH + h * 32;
#pragma unroll
        for (int k = 0; k < 8; k++) {
            float4 v;
            v.x = rp[4 * k + 0] + bias_sm[h * 32 + 4 * k + 0];
            v.y = rp[4 * k + 1] + bias_sm[h * 32 + 4 * k + 1];
            v.z = rp[4 * k + 2] + bias_sm[h * 32 + 4 * k + 2];
            v.w = rp[4 * k + 3] + bias_sm[h * 32 + 4 * k + 3];
            *(float4*)(op + 4 * k) = v;
        }
    }
#pragma unroll
    for (int j = 0; j < 8; j++) {
        int c = wid * 8 + j;
        float bval = bias_sm[c];
        float s = 0, q = 0;
#pragma unroll
        for (int sy = 0; sy < 4; sy++) {
            float v = res[(sy * 32 + lane) * RES_PITCH + c] + bval;
            s += v; q += v * v;
        }
#pragma unroll
        for (int o = 16; o > 0; o >>= 1) {
            s += __shfl_xor_sync(0xffffffff, s, o);
            q += __shfl_xor_sync(0xffffffff, q, o);
        }
        if (lane == 0) { atomicAdd(&gsum[c], s); atomicAdd(&gsumsq[c], q); }
    }
}

// ---------------- final: devox(BN2+lrelu on the fly) + BN(p)+lrelu + add ----
__global__ void final_k(const float* __restrict__ vT, const float* __restrict__ pT,
                        const float* __restrict__ normc,
                        const float* __restrict__ sc2, const float* __restrict__ sh2,
                        const float* __restrict__ scp, const float* __restrict__ shp,
                        float* __restrict__ out) {
    __shared__ float res[64][65];
    __shared__ int cidx[64][8];
    __shared__ float cw[64][8];
    int b = blockIdx.y;
    int n0 = blockIdx.x * 64;
    int t = threadIdx.x;

    if (t < 64) {
        int n = n0 + t;
        float xs = normc[(b * 3 + 0) * NP + n];
        float ys = normc[(b * 3 + 1) * NP + n];
        float zs = normc[(b * 3 + 2) * NP + n];
        float x0f = floorf(xs), y0f = floorf(ys), z0f = floorf(zs);
        float fx = xs - x0f, fy = ys - y0f, fz = zs - z0f;
        int x0 = (int)x0f, y0 = (int)y0f, z0 = (int)z0f;
        int x1 = min(x0 + 1, 31), y1 = min(y0 + 1, 31), z1 = min(z0 + 1, 31);
#pragma unroll
        for (int k = 0; k < 8; k++) {
            int dx = (k >> 2) & 1, dy = (k >> 1) & 1, dz = k & 1;
            float wt = (dx ? fx : 1.0f - fx) * (dy ? fy : 1.0f - fy) * (dz ? fz : 1.0f - fz);
            int idx = ((dx ? x1 : x0) * 32 + (dy ? y1 : y0)) * 32 + (dz ? z1 : z0);
            cidx[t][k] = idx;
            cw[t][k] = wt;
        }
    }
    __syncthreads();

    int c = t & 63, ty = t >> 6;
    float sc2v = sc2[c], sh2v = sh2[c];
    float scpv = scp[c], shpv = shp[c];

    for (int j = ty; j < 64; j += 4) {
        float acc = 0.0f;
#pragma unroll
        for (int k = 0; k < 8; k++) {
            float g = vT[((size_t)b * NV + cidx[j][k]) * CC + c];
            float u = fmaf(g, sc2v, sh2v);
            u = u >= 0 ? u : ALPHA * u;
            acc += cw[j][k] * u;
        }
        float pv = fmaf(pT[((size_t)b * NP + n0 + j) * CC + c], scpv, shpv);
        pv = pv >= 0 ? pv : ALPHA * pv;
        res[c][j] = acc + pv;
    }
    __syncthreads();

    for (int i = t; i < 4096; i += 256) {
        int c2 = i >> 6, j = i & 63;
        out[((size_t)b * CC + c2) * NP + n0 + j] = res[c2][j];
    }
}

// ---------------- launcher ----------------
extern "C" void kernel_launch(void* const* d_in, const int* in_sizes, int n_in,
                              void* d_out, int out_size) {
    const float* feat   = (const float*)d_in[0];
    const float* coords = (const float*)d_in[1];
    const float* c1w    = (const float*)d_in[2];
    const float* c1b    = (const float*)d_in[3];
    const float* g1     = (const float*)d_in[4];
    const float* b1     = (const float*)d_in[5];
    const float* c2w    = (const float*)d_in[6];
    const float* c2b    = (const float*)d_in[7];
    const float* g2     = (const float*)d_in[8];
    const float* b2     = (const float*)d_in[9];
    const float* pw     = (const float*)d_in[10];
    const float* pb     = (const float*)d_in[11];
    const float* pg     = (const float*)d_in[12];
    const float* pbeta  = (const float*)d_in[13];
    float* out = (float*)d_out;

    float *fT, *tmp, *cnt, *bufB, *pT, *normc, *cmean, *stats, *scsh;
    unsigned* cmaxb;
    cudaGetSymbolAddress((void**)&fT, g_fT);
    cudaGetSymbolAddress((void**)&tmp, g_tmp);
    cudaGetSymbolAddress((void**)&cnt, g_cnt);
    cudaGetSymbolAddress((void**)&bufB, g_bufB);
    cudaGetSymbolAddress((void**)&pT, g_pT);
    cudaGetSymbolAddress((void**)&normc, g_normc);
    cudaGetSymbolAddress((void**)&cmean, g_cmean);
    cudaGetSymbolAddress((void**)&cmaxb, g_cmaxb);
    cudaGetSymbolAddress((void**)&stats, g_stats);
    cudaGetSymbolAddress((void**)&scsh, g_scsh);

    float* sum1 = stats + 0 * CC;  float* sq1 = stats + 1 * CC;
    float* sum2 = stats + 2 * CC;  float* sq2 = stats + 3 * CC;
    float* psum = stats + 4 * CC;  float* psq = stats + 5 * CC;
    float* sc1 = scsh + 0 * CC;    float* sh1 = scsh + 1 * CC;
    float* sc2 = scsh + 2 * CC;    float* sh2 = scsh + 3 * CC;
    float* scp = scsh + 4 * CC;    float* shp = scsh + 5 * CC;

    cudaFuncSetAttribute(conv3d_mma<0>, cudaFuncAttributeMaxDynamicSharedMemorySize, CONV_DYN);
    cudaFuncSetAttribute(conv3d_mma<2>, cudaFuncAttributeMaxDynamicSharedMemorySize, CONV_DYN);
    cudaFuncSetAttribute(pgemm_mma, cudaFuncAttributeMaxDynamicSharedMemorySize, PG_DYN);

    const float invV = 1.0f / (float)(BB * NV);
    const float invP = 1.0f / (float)(BB * NP);

    // voxelize
    zero_kernel<<<8192, 256>>>(tmp, (size_t)BB * NV * CC);
    zero_kernel<<<256, 256>>>(cnt, (size_t)BB * NV);
    zero_small<<<1, 512>>>(stats, cmean, cmaxb);
    transpose_feat<<<dim3(NP / 32, BB), 256>>>(feat, fT);
    coord_mean_p<<<dim3(32, BB), 256>>>(coords, cmean);
    coord_max_p<<<dim3(32, BB), 256>>>(coords, cmean, cmaxb);
    scatter<<<BB * NP / 4, 256>>>(coords, fT, cmean, cmaxb, normc, tmp, cnt);

    // conv1: voxel sums+counts in (finalize fused), channels-last out
    conv3d_mma<0><<<dim3(8, 32, BB), 256, CONV_DYN>>>(tmp, cnt, bufB, c1w, c1b,
                                                      nullptr, nullptr, sum1, sq1);
    mkscale<<<1, 64>>>(sum1, sq1, g1, b1, invV, sc1, sh1);

    // conv2: channels-last in with BN1+lrelu fused, channels-last out into tmp
    conv3d_mma<2><<<dim3(8, 32, BB), 256, CONV_DYN>>>(bufB, nullptr, tmp, c2w, c2b,
                                                      sc1, sh1, sum2, sq2);
    mkscale<<<1, 64>>>(sum2, sq2, g2, b2, invV, sc2, sh2);

    // point branch: tensor-core GEMM + fused stats
    pgemm_mma<<<dim3(NP / 128, BB), 256, PG_DYN>>>(fT, pw, pb, pT, psum, psq);
    mkscale<<<1, 64>>>(psum, psq, pg, pbeta, invP, scp, shp);

    // devoxelize (BN2+lrelu applied on gather) + point BN + add
    final_k<<<dim3(NP / 64, BB), 256>>>(tmp, pT, normc, sc2, sh2, scp, shp, out);

    // coords passthrough (second tuple output), if the harness expects it
    int main_sz = BB * CC * NP;
    int coord_sz = BB * 3 * NP;
    if (out_size >= main_sz + coord_sz)
        copy_kernel<<<coord_sz / 256, 256>>>(coords, out + main_sz, coord_sz);
}

// round 12
// speedup vs baseline: 1.1809x; 1.1809x over previous
#include <cuda_runtime.h>
#include <cuda_fp16.h>

#define BB 8
#define CC 64
#define NP 16384
#define RR 32
#define NV 32768          // 32^3
#define ALPHA 0.1f
#define BNEPS 1e-4f
#define VOXEPS 1e-6f

// ---------------- scratch (device globals; no allocation allowed) ----------
__device__ float g_fT[BB * NP * CC];        // features transposed [b][n][c]
__device__ float g_tmp[BB * NV * CC];       // voxel sums [b][v][c]; later raw conv2 out
__device__ float g_cnt[BB * NV];            // voxel counts
__device__ float g_bufB[BB * CC * NV];      // conv1 output (channels-last [b][v][c])
__device__ float g_pT[BB * NP * CC];        // point branch [b][n][c]
__device__ float g_normc[BB * 3 * NP];      // normalized coords in [0,31]
__device__ float g_cmean[BB * 3];           // coordinate SUMS
__device__ unsigned g_cmaxb[BB];            // max dist^2 as float bits
__device__ float g_stats[6 * CC];           // sum1,sq1,sum2,sq2,psum,psq
__device__ float g_scsh[6 * CC];            // sc1,sh1,sc2,sh2,scp,shp

// ---------------- utility kernels ----------------
__global__ void zero_kernel(float* p, size_t n) {
    size_t i = (size_t)blockIdx.x * blockDim.x + threadIdx.x;
    size_t stride = (size_t)gridDim.x * blockDim.x;
    for (; i < n; i += stride) p[i] = 0.0f;
}

__global__ void zero_small(float* stats, float* cmean, unsigned* cmaxb) {
    int t = threadIdx.x;
    if (t < 6 * CC) stats[t] = 0.0f;
    if (t < BB * 3) cmean[t] = 0.0f;
    if (t < BB) cmaxb[t] = 0u;
}

__global__ void copy_kernel(const float* __restrict__ src, float* __restrict__ dst, int n) {
    int i = blockIdx.x * blockDim.x + threadIdx.x;
    int stride = gridDim.x * blockDim.x;
    for (; i < n; i += stride) dst[i] = src[i];
}

__global__ void mkscale(const float* __restrict__ sum, const float* __restrict__ sumsq,
                        const float* __restrict__ gamma, const float* __restrict__ beta,
                        float invcnt, float* __restrict__ sc, float* __restrict__ sh) {
    int c = threadIdx.x;
    float mean = sum[c] * invcnt;
    float var = sumsq[c] * invcnt - mean * mean;
    float s = gamma[c] * rsqrtf(var + BNEPS);
    sc[c] = s;
    sh[c] = beta[c] - mean * s;
}

// ---------------- features transpose [b][c][n] -> [b][n][c] ----------------
__global__ void transpose_feat(const float* __restrict__ feat, float* __restrict__ fT) {
    __shared__ float s[CC][33];
    int b = blockIdx.y;
    int n0 = blockIdx.x * 32;
    int t = threadIdx.x;
    for (int i = t; i < 32 * 64; i += 256) {
        int c = i >> 5, n = i & 31;
        s[c][n] = feat[(b * CC + c) * NP + n0 + n];
    }
    __syncthreads();
    for (int i = t; i < 32 * 64; i += 256) {
        int n = i >> 6, c = i & 63;
        fT[((size_t)b * NP + n0 + n) * CC + c] = s[c][n];
    }
}

// ---------------- coord statistics ----------------
__global__ void coord_mean_p(const float* __restrict__ coords, float* __restrict__ cmean) {
    int b = blockIdx.y;
    int n0 = blockIdx.x * 512;
    int t = threadIdx.x;
    float s0 = 0, s1 = 0, s2 = 0;
    for (int n = n0 + t; n < n0 + 512; n += 256) {
        s0 += coords[(b * 3 + 0) * NP + n];
        s1 += coords[(b * 3 + 1) * NP + n];
        s2 += coords[(b * 3 + 2) * NP + n];
    }
#pragma unroll
    for (int o = 16; o > 0; o >>= 1) {
        s0 += __shfl_xor_sync(0xffffffff, s0, o);
        s1 += __shfl_xor_sync(0xffffffff, s1, o);
        s2 += __shfl_xor_sync(0xffffffff, s2, o);
    }
    if ((t & 31) == 0) {
        atomicAdd(&cmean[b * 3 + 0], s0);
        atomicAdd(&cmean[b * 3 + 1], s1);
        atomicAdd(&cmean[b * 3 + 2], s2);
    }
}

__global__ void coord_max_p(const float* __restrict__ coords, const float* __restrict__ cmean,
                            unsigned* __restrict__ cmaxb) {
    int b = blockIdx.y;
    int n0 = blockIdx.x * 512;
    int t = threadIdx.x;
    float invn = 1.0f / (float)NP;
    float mx = cmean[b * 3 + 0] * invn, my = cmean[b * 3 + 1] * invn, mz = cmean[b * 3 + 2] * invn;
    float m = 0.0f;
    for (int n = n0 + t; n < n0 + 512; n += 256) {
        float dx = coords[(b * 3 + 0) * NP + n] - mx;
        float dy = coords[(b * 3 + 1) * NP + n] - my;
        float dz = coords[(b * 3 + 2) * NP + n] - mz;
        m = fmaxf(m, dx * dx + dy * dy + dz * dz);
    }
#pragma unroll
    for (int o = 16; o > 0; o >>= 1) m = fmaxf(m, __shfl_xor_sync(0xffffffff, m, o));
    if ((t & 31) == 0) atomicMax(&cmaxb[b], __float_as_uint(m));
}

// ---------------- voxelize scatter ----------------
__global__ void scatter(const float* __restrict__ coords, const float* __restrict__ fT,
                        const float* __restrict__ cmean, const unsigned* __restrict__ cmaxb,
                        float* __restrict__ normc, float* __restrict__ tmp,
                        float* __restrict__ cnt) {
    int t = threadIdx.x;
    int pi = blockIdx.x * 4 + (t >> 6);
    int c = t & 63;
    int b = pi / NP;
    int n = pi - b * NP;

    float invn = 1.0f / (float)NP;
    float r = sqrtf(__uint_as_float(cmaxb[b]));
    float inv = 1.0f / (2.0f * r + VOXEPS);
    float nx = (coords[(b * 3 + 0) * NP + n] - cmean[b * 3 + 0] * invn) * inv + 0.5f;
    float ny = (coords[(b * 3 + 1) * NP + n] - cmean[b * 3 + 1] * invn) * inv + 0.5f;
    float nz = (coords[(b * 3 + 2) * NP + n] - cmean[b * 3 + 2] * invn) * inv + 0.5f;
    nx = fminf(fmaxf(nx * (float)RR, 0.0f), (float)(RR - 1));
    ny = fminf(fmaxf(ny * (float)RR, 0.0f), (float)(RR - 1));
    nz = fminf(fmaxf(nz * (float)RR, 0.0f), (float)(RR - 1));
    int vx = __float2int_rn(nx), vy = __float2int_rn(ny), vz = __float2int_rn(nz);
    int v = (vx * RR + vy) * RR + vz;

    float f = fT[((size_t)b * NP + n) * CC + c];
    atomicAdd(&tmp[((size_t)b * NV + v) * CC + c], f);
    if (c == 0) atomicAdd(&cnt[b * NV + v], 1.0f);
    if (c < 3) normc[(b * 3 + c) * NP + n] = (c == 0 ? nx : (c == 1 ? ny : nz));
}

// ================= fp16 mma.sync conv (m16n8k16, baseline PTX) =============
// CTA: M=128 spatial (4y x 32x) x N=64 cout, fixed (z,b). 8 warps, each 32x32.
// INMODE 0: input = voxel sums [b][v][c] / max(cnt,1)  (fuses finalize_vox)
// INMODE 2: input = channels-last [b][v][c] with BN+lrelu applied at load
// A/B stored as half2 (consecutive ci pairs) -> smem bytes & MMA count halved.
// Slab rows pitch 20 u32 (16 half2 data + 4 pad) -> conflict-free LDS32.

static __device__ __forceinline__ float tf32_rna(float v) {
    unsigned u;
    asm("cvt.rna.tf32.f32 %0, %1;" : "=r"(u) : "f"(v));
    return __uint_as_float(u);
}

#define LDS32(dst, addr) asm volatile("ld.shared.b32 %0, [%1];" : "=r"(dst) : "r"(addr))
#define MMA_TF32(d, a0, a1, a2, a3, b0, b1)                                   \
    asm volatile(                                                             \
        "mma.sync.aligned.m16n8k8.row.col.f32.tf32.tf32.f32 "                 \
        "{%0,%1,%2,%3}, {%4,%5,%6,%7}, {%8,%9}, {%0,%1,%2,%3};"               \
        : "+f"(d[0]), "+f"(d[1]), "+f"(d[2]), "+f"(d[3])                      \
        : "r"(a0), "r"(a1), "r"(a2), "r"(a3), "r"(b0), "r"(b1))
#define MMA_F16(d, a0, a1, a2, a3, b0, b1)                                    \
    asm volatile(                                                             \
        "mma.sync.aligned.m16n8k16.row.col.f32.f16.f16.f32 "                  \
        "{%0,%1,%2,%3}, {%4,%5,%6,%7}, {%8,%9}, {%0,%1,%2,%3};"               \
        : "+f"(d[0]), "+f"(d[1]), "+f"(d[2]), "+f"(d[3])                      \
        : "r"(a0), "r"(a1), "r"(a2), "r"(a3), "r"(b0), "r"(b1))

#define CWF 1280          // W' u32 per buffer: 64 n-rows x 20
#define CSLAB 12240       // slab u32: 612 rows x 20
#define RES_PITCH 68
#define CONV_DYN ((2 * CWF + CSLAB) * 4)   // 59200 B

template <int INMODE>
__global__ __launch_bounds__(256, 2)
void conv3d_mma(const float* __restrict__ in, const float* __restrict__ cnt,
                float* __restrict__ out,
                const float* __restrict__ w, const float* __restrict__ bias,
                const float* __restrict__ insc, const float* __restrict__ insh,
                float* __restrict__ gsum, float* __restrict__ gsumsq) {
    extern __shared__ __align__(16) float dsm[];
    __shared__ float sc_sm[64], sh_sm[64], bias_sm[64];

    unsigned* wsm0 = (unsigned*)dsm;
    unsigned* wsm1 = (unsigned*)dsm + CWF;
    unsigned* slab = (unsigned*)dsm + 2 * CWF;
    float* res = (float*)slab;  // reused after compute (128 x 68 <= 12240)

    int b = blockIdx.z, z0 = blockIdx.y, y0 = blockIdx.x * 4;
    int t = threadIdx.x, lane = t & 31, wid = t >> 5;
    int wy = wid >> 1, wn = wid & 1;
    int gid = lane >> 2, tig = lane & 3;

    unsigned slab_s = (unsigned)__cvta_generic_to_shared(slab);
    unsigned wsm_s[2] = {(unsigned)__cvta_generic_to_shared(wsm0),
                         (unsigned)__cvta_generic_to_shared(wsm1)};

    if (t < 64) {
        bias_sm[t] = bias[t];
        if (INMODE == 2) { sc_sm[t] = insc[t]; sh_sm[t] = insh[t]; }
    }
    __syncthreads();

    float acc[2][4][4];
#pragma unroll
    for (int mt = 0; mt < 2; mt++)
#pragma unroll
        for (int nt = 0; nt < 4; nt++)
#pragma unroll
            for (int e = 0; e < 4; e++) acc[mt][nt][e] = 0.0f;

    // slab: row r = (zs*6+ys)*34+xs, 16 half2 (32 ci) per row, pitch 20 u32
    auto load_slab = [&](int cig) {
        for (int i = t; i < 4896; i += 256) {
            int zy = i / 272, r = i - zy * 272;
            int c4 = r / 34, xs = r - c4 * 34;
            int zs = zy / 6, ys = zy - zs * 6;
            int zg = z0 - 1 + zs, yg = y0 - 1 + ys, xg = xs - 1;
            bool ok = (unsigned)zg < 32u && (unsigned)yg < 32u && (unsigned)xg < 32u;
            int vox = zg * 1024 + yg * 32 + xg;
            float4 v;
            if (INMODE == 0) {
                float4 sums = ok ? __ldg((const float4*)(in + ((size_t)b * NV + vox) * CC
                                                          + cig * 32 + c4 * 4))
                                 : make_float4(0.f, 0.f, 0.f, 0.f);
                float inv = ok ? 1.0f / fmaxf(__ldg(cnt + (size_t)b * NV + vox), 1.0f) : 0.0f;
                v.x = sums.x * inv; v.y = sums.y * inv;
                v.z = sums.z * inv; v.w = sums.w * inv;
            } else {
                v = ok ? __ldg((const float4*)(in + ((size_t)b * NV + vox) * CC
                                                + cig * 32 + c4 * 4))
                       : make_float4(0.f, 0.f, 0.f, 0.f);
                int c = cig * 32 + c4 * 4;
                float u;
                u = fmaf(v.x, sc_sm[c + 0], sh_sm[c + 0]); v.x = u >= 0 ? u : ALPHA * u;
                u = fmaf(v.y, sc_sm[c + 1], sh_sm[c + 1]); v.y = u >= 0 ? u : ALPHA * u;
                u = fmaf(v.z, sc_sm[c + 2], sh_sm[c + 2]); v.z = u >= 0 ? u : ALPHA * u;
                u = fmaf(v.w, sc_sm[c + 3], sh_sm[c + 3]); v.w = u >= 0 ? u : ALPHA * u;
                if (!ok) v = make_float4(0.f, 0.f, 0.f, 0.f);  // pad AFTER transform
            }
            __half2 h0 = __floats2half2_rn(v.x, v.y);   // low = even ci
            __half2 h1 = __floats2half2_rn(v.z, v.w);
            uint2 uu;
            uu.x = *(unsigned*)&h0;
            uu.y = *(unsigned*)&h1;
            int row = (zs * 6 + ys) * 34 + xs;
            *(uint2*)(slab + row * 20 + c4 * 2) = uu;
        }
    };

    // W' staging: row co (64), half2 slot k2 (16) at u32 offset k2, pitch 20
    float wlo[4], whi[4];
    auto w_prefetch = [&](int cig, int koff) {
        const float* wb = w + (size_t)(koff * 64 + cig * 32) * 64;
#pragma unroll
        for (int j = 0; j < 4; j++) {
            int e = t + j * 256;
            int k2 = e >> 6, co = e & 63;
            wlo[j] = __ldg(wb + (size_t)(2 * k2) * 64 + co);
            whi[j] = __ldg(wb + (size_t)(2 * k2 + 1) * 64 + co);
        }
    };
    auto w_sts = [&](unsigned* dst) {
#pragma unroll
        for (int j = 0; j < 4; j++) {
            int e = t + j * 256;
            int k2 = e >> 6, co = e & 63;
            __half2 h = __floats2half2_rn(wlo[j], whi[j]);
            dst[co * 20 + k2] = *(unsigned*)&h;
        }
    };

    auto compute = [&](int buf, int koff) {
        int dz = koff / 9, rem = koff - dz * 9;
        int dy = rem / 3, dx = rem - dy * 3;
        unsigned a_base = slab_s +
            (unsigned)((((dz * 6 + wy + dy) * 34) + gid + dx) * 20 + tig) * 4;
        unsigned b_base = wsm_s[buf] + (unsigned)((wn * 32 + gid) * 20 + tig) * 4;
#pragma unroll
        for (int ks = 0; ks < 2; ks++) {
            unsigned ab = a_base + ks * 32;
            unsigned bb = b_base + ks * 32;
            unsigned a0, a1, a2, a3, a4, a5, a6, a7;
            LDS32(a0, ab);            LDS32(a1, ab + 640);   // x+8 rows
            LDS32(a2, ab + 16);       LDS32(a3, ab + 656);   // k2+4
            LDS32(a4, ab + 1280);     LDS32(a5, ab + 1920);  // mtile1 (x+16)
            LDS32(a6, ab + 1296);     LDS32(a7, ab + 1936);
            unsigned b0[4], b1[4];
#pragma unroll
            for (int nt = 0; nt < 4; nt++) {
                LDS32(b0[nt], bb + nt * 640);
                LDS32(b1[nt], bb + nt * 640 + 16);
            }
#pragma unroll
            for (int nt = 0; nt < 4; nt++) {
                MMA_F16(acc[0][nt], a0, a1, a2, a3, b0[nt], b1[nt]);
                MMA_F16(acc[1][nt], a4, a5, a6, a7, b0[nt], b1[nt]);
            }
        }
    };

#pragma unroll 1
    for (int cig = 0; cig < 2; cig++) {
        load_slab(cig);
        w_prefetch(cig, 0);
        w_sts(wsm0);
        __syncthreads();
#pragma unroll 1
        for (int koff = 0; koff < 27; koff++) {
            if (koff < 26) w_prefetch(cig, koff + 1);
            compute(koff & 1, koff);
            if (koff < 26) w_sts((koff & 1) ? wsm0 : wsm1);
            __syncthreads();
        }
    }

    // ---- epilogue: bounce D to smem; channels-last store + fused BN stats ----
#pragma unroll
    for (int mt = 0; mt < 2; mt++)
#pragma unroll
        for (int nt = 0; nt < 4; nt++) {
            int spat0 = wy * 32 + mt * 16 + gid;
            int cout0 = wn * 32 + nt * 8 + tig * 2;
            *(float2*)(res + spat0 * RES_PITCH + cout0) =
                make_float2(acc[mt][nt][0], acc[mt][nt][1]);
            *(float2*)(res + (spat0 + 8) * RES_PITCH + cout0) =
                make_float2(acc[mt][nt][2], acc[mt][nt][3]);
        }
    __syncthreads();

    {
        int s_ = t >> 1, h = t & 1;
        int vox = z0 * 1024 + (y0 + (s_ >> 5)) * 32 + (s_ & 31);
        float* op = out + ((size_t)b * NV + vox) * CC + h * 32;
        const float* rp = res + s_ * RES_PITCH + h * 32;
#pragma unroll
        for (int k = 0; k < 8; k++) {
            float4 v;
            v.x = rp[4 * k + 0] + bias_sm[h * 32 + 4 * k + 0];
            v.y = rp[4 * k + 1] + bias_sm[h * 32 + 4 * k + 1];
            v.z = rp[4 * k + 2] + bias_sm[h * 32 + 4 * k + 2];
            v.w = rp[4 * k + 3] + bias_sm[h * 32 + 4 * k + 3];
            *(float4*)(op + 4 * k) = v;
        }
    }
#pragma unroll
    for (int j = 0; j < 8; j++) {
        int c = wid * 8 + j;
        float bval = bias_sm[c];
        float s = 0, q = 0;
#pragma unroll
        for (int sy = 0; sy < 4; sy++) {
            float v = res[(sy * 32 + lane) * RES_PITCH + c] + bval;
            s += v; q += v * v;
        }
#pragma unroll
        for (int o = 16; o > 0; o >>= 1) {
            s += __shfl_xor_sync(0xffffffff, s, o);
            q += __shfl_xor_sync(0xffffffff, q, o);
        }
        if (lane == 0) { atomicAdd(&gsum[c], s); atomicAdd(&gsumsq[c], q); }
    }
}

// ================= tf32 mma.sync point GEMM + fused stats (R9, proven) =====
#define PGW_FLOATS 2304   // 32 ci x 72 pitch
#define PG_A_FLOATS (2 * 128 * 36)    // 9216
#define PG_DYN ((PG_A_FLOATS + 2 * PGW_FLOATS) * 4)   // 55296 B

__global__ __launch_bounds__(256, 2)
void pgemm_mma(const float* __restrict__ fT, const float* __restrict__ w,
               const float* __restrict__ bias, float* __restrict__ pT,
               float* __restrict__ gsum, float* __restrict__ gsumsq) {
    extern __shared__ __align__(16) float dsm[];
    __shared__ float bias_sm[64];
    float* asm0 = dsm;                       // [cig][128][36]
    float* wsm0 = dsm + PG_A_FLOATS;         // [cig][32][72]
    float* res = dsm;                        // reuse after compute

    int b = blockIdx.y;
    int n0 = blockIdx.x * 128;
    int t = threadIdx.x, lane = t & 31, wid = t >> 5;
    int wy = wid >> 1, wn = wid & 1;
    int gid = lane >> 2, tig = lane & 3;

    unsigned a_s = (unsigned)__cvta_generic_to_shared(asm0);
    unsigned w_s = (unsigned)__cvta_generic_to_shared(wsm0);

    if (t < 64) bias_sm[t] = bias[t];

    for (int i = t; i < 2048; i += 256) {
        int n = i >> 4, c4 = i & 15;
        int cig = c4 >> 3, c4l = c4 & 7;
        float4 v = __ldg((const float4*)(fT + ((size_t)b * NP + n0 + n) * CC + c4 * 4));
        v.x = tf32_rna(v.x); v.y = tf32_rna(v.y);
        v.z = tf32_rna(v.z); v.w = tf32_rna(v.w);
        *(float4*)(asm0 + (size_t)cig * 128 * 36 + n * 36 + c4l * 4) = v;
    }
    {
        const float4* wg = (const float4*)w;
#pragma unroll
        for (int k = 0; k < 4; k++) {
            float4 v = __ldg(&wg[t + k * 256]);
            int e = (t + k * 256) * 4;
            int ci = e >> 6, co = e & 63;
            float* d = wsm0 + (size_t)(ci >> 5) * PGW_FLOATS + (ci & 31) * 72 + co;
            d[0] = tf32_rna(v.x); d[1] = tf32_rna(v.y);
            d[2] = tf32_rna(v.z); d[3] = tf32_rna(v.w);
        }
    }
    __syncthreads();

    float acc[2][4][4];
#pragma unroll
    for (int mt = 0; mt < 2; mt++)
#pragma unroll
        for (int nt = 0; nt < 4; nt++)
#pragma unroll
            for (int e = 0; e < 4; e++) acc[mt][nt][e] = 0.0f;

#pragma unroll
    for (int cig = 0; cig < 2; cig++) {
        unsigned a_base = a_s + (unsigned)(cig * 128 * 36 + (wy * 32 + gid) * 36 + tig) * 4;
        unsigned b_base = w_s + (unsigned)(cig * PGW_FLOATS + tig * 72 + wn * 32 + gid) * 4;
#pragma unroll
        for (int ks = 0; ks < 4; ks++) {
            unsigned ab = a_base + ks * 32;
            unsigned bb = b_base + ks * 2304;
            unsigned a0, a1, a2, a3, a4, a5, a6, a7;
            LDS32(a0, ab);            LDS32(a1, ab + 1152);
            LDS32(a2, ab + 16);       LDS32(a3, ab + 1168);
            LDS32(a4, ab + 2304);     LDS32(a5, ab + 3456);
            LDS32(a6, ab + 2320);     LDS32(a7, ab + 3472);
            unsigned b0[4], b1[4];
#pragma unroll
            for (int nt = 0; nt < 4; nt++) {
                LDS32(b0[nt], bb + nt * 32);
                LDS32(b1[nt], bb + nt * 32 + 1152);
            }
#pragma unroll
            for (int nt = 0; nt < 4; nt++) {
                MMA_TF32(acc[0][nt], a0, a1, a2, a3, b0[nt], b1[nt]);
                MMA_TF32(acc[1][nt], a4, a5, a6, a7, b0[nt], b1[nt]);
            }
        }
    }
    __syncthreads();

#pragma unroll
    for (int mt = 0; mt < 2; mt++)
#pragma unroll
        for (int nt = 0; nt < 4; nt++) {
            int spat0 = wy * 32 + mt * 16 + gid;
            int cout0 = wn * 32 + nt * 8 + tig * 2;
            *(float2*)(res + spat0 * RES_PITCH + cout0) =
                make_float2(acc[mt][nt][0], acc[mt][nt][1]);
            *(float2*)(res + (spat0 + 8) * RES_PITCH + cout0) =
                make_float2(acc[mt][nt][2], acc[mt][nt][3]);
        }
    __syncthreads();

    {
        int s_ = t >> 1, h = t & 1;
        float* op = pT + ((size_t)b * NP + n0 + s_) * CC + h * 32;
        const float* rp = res + s_ * RES_PITCH + h * 32;
#pragma unroll
        for (int k = 0; k < 8; k++) {
            float4 v;
            v.x = rp[4 * k + 0] + bias_sm[h * 32 + 4 * k + 0];
            v.y = rp[4 * k + 1] + bias_sm[h * 32 + 4 * k + 1];
            v.z = rp[4 * k + 2] + bias_sm[h * 32 + 4 * k + 2];
            v.w = rp[4 * k + 3] + bias_sm[h * 32 + 4 * k + 3];
            *(float4*)(op + 4 * k) = v;
        }
    }
#pragma unroll
    for (int j = 0; j < 8; j++) {
        int c = wid * 8 + j;
        float bval = bias_sm[c];
        float s = 0, q = 0;
#pragma unroll
        for (int sy = 0; sy < 4; sy++) {
            float v = res[(sy * 32 + lane) * RES_PITCH + c] + bval;
            s += v; q += v * v;
        }
#pragma unroll
        for (int o = 16; o > 0; o >>= 1) {
            s += __shfl_xor_sync(0xffffffff, s, o);
            q += __shfl_xor_sync(0xffffffff, q, o);
        }
        if (lane == 0) { atomicAdd(&gsum[c], s); atomicAdd(&gsumsq[c], q); }
    }
}

// ---------------- final: devox(BN2+lrelu on the fly) + BN(p)+lrelu + add ----
__global__ void final_k(const float* __restrict__ vT, const float* __restrict__ pT,
                        const float* __restrict__ normc,
                        const float* __restrict__ sc2, const float* __restrict__ sh2,
                        const float* __restrict__ scp, const float* __restrict__ shp,
                        float* __restrict__ out) {
    __shared__ float res[64][65];
    __shared__ int cidx[64][8];
    __shared__ float cw[64][8];
    int b = blockIdx.y;
    int n0 = blockIdx.x * 64;
    int t = threadIdx.x;

    if (t < 64) {
        int n = n0 + t;
        float xs = normc[(b * 3 + 0) * NP + n];
        float ys = normc[(b * 3 + 1) * NP + n];
        float zs = normc[(b * 3 + 2) * NP + n];
        float x0f = floorf(xs), y0f = floorf(ys), z0f = floorf(zs);
        float fx = xs - x0f, fy = ys - y0f, fz = zs - z0f;
        int x0 = (int)x0f, y0 = (int)y0f, z0 = (int)z0f;
        int x1 = min(x0 + 1, 31), y1 = min(y0 + 1, 31), z1 = min(z0 + 1, 31);
#pragma unroll
        for (int k = 0; k < 8; k++) {
            int dx = (k >> 2) & 1, dy = (k >> 1) & 1, dz = k & 1;
            float wt = (dx ? fx : 1.0f - fx) * (dy ? fy : 1.0f - fy) * (dz ? fz : 1.0f - fz);
            int idx = ((dx ? x1 : x0) * 32 + (dy ? y1 : y0)) * 32 + (dz ? z1 : z0);
            cidx[t][k] = idx;
            cw[t][k] = wt;
        }
    }
    __syncthreads();

    int c = t & 63, ty = t >> 6;
    float sc2v = sc2[c], sh2v = sh2[c];
    float scpv = scp[c], shpv = shp[c];

    for (int j = ty; j < 64; j += 4) {
        float acc = 0.0f;
#pragma unroll
        for (int k = 0; k < 8; k++) {
            float g = vT[((size_t)b * NV + cidx[j][k]) * CC + c];
            float u = fmaf(g, sc2v, sh2v);
            u = u >= 0 ? u : ALPHA * u;
            acc += cw[j][k] * u;
        }
        float pv = fmaf(pT[((size_t)b * NP + n0 + j) * CC + c], scpv, shpv);
        pv = pv >= 0 ? pv : ALPHA * pv;
        res[c][j] = acc + pv;
    }
    __syncthreads();

    for (int i = t; i < 4096; i += 256) {
        int c2 = i >> 6, j = i & 63;
        out[((size_t)b * CC + c2) * NP + n0 + j] = res[c2][j];
    }
}

// ---------------- launcher ----------------
extern "C" void kernel_launch(void* const* d_in, const int* in_sizes, int n_in,
                              void* d_out, int out_size) {
    const float* feat   = (const float*)d_in[0];
    const float* coords = (const float*)d_in[1];
    const float* c1w    = (const float*)d_in[2];
    const float* c1b    = (const float*)d_in[3];
    const float* g1     = (const float*)d_in[4];
    const float* b1     = (const float*)d_in[5];
    const float* c2w    = (const float*)d_in[6];
    const float* c2b    = (const float*)d_in[7];
    const float* g2     = (const float*)d_in[8];
    const float* b2     = (const float*)d_in[9];
    const float* pw     = (const float*)d_in[10];
    const float* pb     = (const float*)d_in[11];
    const float* pg     = (const float*)d_in[12];
    const float* pbeta  = (const float*)d_in[13];
    float* out = (float*)d_out;

    float *fT, *tmp, *cnt, *bufB, *pT, *normc, *cmean, *stats, *scsh;
    unsigned* cmaxb;
    cudaGetSymbolAddress((void**)&fT, g_fT);
    cudaGetSymbolAddress((void**)&tmp, g_tmp);
    cudaGetSymbolAddress((void**)&cnt, g_cnt);
    cudaGetSymbolAddress((void**)&bufB, g_bufB);
    cudaGetSymbolAddress((void**)&pT, g_pT);
    cudaGetSymbolAddress((void**)&normc, g_normc);
    cudaGetSymbolAddress((void**)&cmean, g_cmean);
    cudaGetSymbolAddress((void**)&cmaxb, g_cmaxb);
    cudaGetSymbolAddress((void**)&stats, g_stats);
    cudaGetSymbolAddress((void**)&scsh, g_scsh);

    float* sum1 = stats + 0 * CC;  float* sq1 = stats + 1 * CC;
    float* sum2 = stats + 2 * CC;  float* sq2 = stats + 3 * CC;
    float* psum = stats + 4 * CC;  float* psq = stats + 5 * CC;
    float* sc1 = scsh + 0 * CC;    float* sh1 = scsh + 1 * CC;
    float* sc2 = scsh + 2 * CC;    float* sh2 = scsh + 3 * CC;
    float* scp = scsh + 4 * CC;    float* shp = scsh + 5 * CC;

    cudaFuncSetAttribute(conv3d_mma<0>, cudaFuncAttributeMaxDynamicSharedMemorySize, CONV_DYN);
    cudaFuncSetAttribute(conv3d_mma<2>, cudaFuncAttributeMaxDynamicSharedMemorySize, CONV_DYN);
    cudaFuncSetAttribute(pgemm_mma, cudaFuncAttributeMaxDynamicSharedMemorySize, PG_DYN);

    const float invV = 1.0f / (float)(BB * NV);
    const float invP = 1.0f / (float)(BB * NP);

    // voxelize
    zero_kernel<<<8192, 256>>>(tmp, (size_t)BB * NV * CC);
    zero_kernel<<<256, 256>>>(cnt, (size_t)BB * NV);
    zero_small<<<1, 512>>>(stats, cmean, cmaxb);
    transpose_feat<<<dim3(NP / 32, BB), 256>>>(feat, fT);
    coord_mean_p<<<dim3(32, BB), 256>>>(coords, cmean);
    coord_max_p<<<dim3(32, BB), 256>>>(coords, cmean, cmaxb);
    scatter<<<BB * NP / 4, 256>>>(coords, fT, cmean, cmaxb, normc, tmp, cnt);

    // conv1: voxel sums+counts in (finalize fused), channels-last out
    conv3d_mma<0><<<dim3(8, 32, BB), 256, CONV_DYN>>>(tmp, cnt, bufB, c1w, c1b,
                                                      nullptr, nullptr, sum1, sq1);
    mkscale<<<1, 64>>>(sum1, sq1, g1, b1, invV, sc1, sh1);

    // conv2: channels-last in with BN1+lrelu fused, channels-last out into tmp
    conv3d_mma<2><<<dim3(8, 32, BB), 256, CONV_DYN>>>(bufB, nullptr, tmp, c2w, c2b,
                                                      sc1, sh1, sum2, sq2);
    mkscale<<<1, 64>>>(sum2, sq2, g2, b2, invV, sc2, sh2);

    // point branch: tensor-core GEMM + fused stats
    pgemm_mma<<<dim3(NP / 128, BB), 256, PG_DYN>>>(fT, pw, pb, pT, psum, psq);
    mkscale<<<1, 64>>>(psum, psq, pg, pbeta, invP, scp, shp);

    // devoxelize (BN2+lrelu applied on gather) + point BN + add
    final_k<<<dim3(NP / 64, BB), 256>>>(tmp, pT, normc, sc2, sh2, scp, shp, out);

    // coords passthrough (second tuple output), if the harness expects it
    int main_sz = BB * CC * NP;
    int coord_sz = BB * 3 * NP;
    if (out_size >= main_sz + coord_sz)
        copy_kernel<<<coord_sz / 256, 256>>>(coords, out + main_sz, coord_sz);
}

// round 13
// speedup vs baseline: 1.3565x; 1.1487x over previous
#include <cuda_runtime.h>
#include <cuda_fp16.h>

#define BB 8
#define CC 64
#define NP 16384
#define RR 32
#define NV 32768          // 32^3
#define ALPHA 0.1f
#define BNEPS 1e-4f
#define VOXEPS 1e-6f

// ---------------- scratch (device globals; no allocation allowed) ----------
__device__ float g_fT[BB * NP * CC];        // features transposed [b][n][c]
__device__ float g_tmp[BB * NV * CC];       // voxel sums [b][v][c]; later raw conv2 out
__device__ float g_cnt[BB * NV];            // voxel counts
__device__ float g_bufB[BB * CC * NV];      // conv1 output (channels-last [b][v][c])
__device__ float g_pT[BB * NP * CC];        // point branch [b][n][c]
__device__ float g_normc[BB * 3 * NP];      // normalized coords in [0,31]
__device__ float g_cmean[BB * 3];           // coordinate SUMS
__device__ unsigned g_cmaxb[BB];            // max dist^2 as float bits
__device__ float g_stats[6 * CC];           // sum1,sq1,sum2,sq2,psum,psq
__device__ float g_scsh[6 * CC];            // sc1,sh1,sc2,sh2,scp,shp

// ---------------- utility kernels ----------------
__global__ void zero_kernel(float* p, size_t n) {
    size_t i = (size_t)blockIdx.x * blockDim.x + threadIdx.x;
    size_t stride = (size_t)gridDim.x * blockDim.x;
    for (; i < n; i += stride) p[i] = 0.0f;
}

__global__ void zero_small(float* stats, float* cmean, unsigned* cmaxb) {
    int t = threadIdx.x;
    if (t < 6 * CC) stats[t] = 0.0f;
    if (t < BB * 3) cmean[t] = 0.0f;
    if (t < BB) cmaxb[t] = 0u;
}

__global__ void copy_kernel(const float* __restrict__ src, float* __restrict__ dst, int n) {
    int i = blockIdx.x * blockDim.x + threadIdx.x;
    int stride = gridDim.x * blockDim.x;
    for (; i < n; i += stride) dst[i] = src[i];
}

__global__ void mkscale(const float* __restrict__ sum, const float* __restrict__ sumsq,
                        const float* __restrict__ gamma, const float* __restrict__ beta,
                        float invcnt, float* __restrict__ sc, float* __restrict__ sh) {
    int c = threadIdx.x;
    float mean = sum[c] * invcnt;
    float var = sumsq[c] * invcnt - mean * mean;
    float s = gamma[c] * rsqrtf(var + BNEPS);
    sc[c] = s;
    sh[c] = beta[c] - mean * s;
}

// ---------------- features transpose [b][c][n] -> [b][n][c] ----------------
__global__ void transpose_feat(const float* __restrict__ feat, float* __restrict__ fT) {
    __shared__ float s[CC][33];
    int b = blockIdx.y;
    int n0 = blockIdx.x * 32;
    int t = threadIdx.x;
    for (int i = t; i < 32 * 64; i += 256) {
        int c = i >> 5, n = i & 31;
        s[c][n] = feat[(b * CC + c) * NP + n0 + n];
    }
    __syncthreads();
    for (int i = t; i < 32 * 64; i += 256) {
        int n = i >> 6, c = i & 63;
        fT[((size_t)b * NP + n0 + n) * CC + c] = s[c][n];
    }
}

// ---------------- coord statistics ----------------
__global__ void coord_mean_p(const float* __restrict__ coords, float* __restrict__ cmean) {
    int b = blockIdx.y;
    int n0 = blockIdx.x * 512;
    int t = threadIdx.x;
    float s0 = 0, s1 = 0, s2 = 0;
    for (int n = n0 + t; n < n0 + 512; n += 256) {
        s0 += coords[(b * 3 + 0) * NP + n];
        s1 += coords[(b * 3 + 1) * NP + n];
        s2 += coords[(b * 3 + 2) * NP + n];
    }
#pragma unroll
    for (int o = 16; o > 0; o >>= 1) {
        s0 += __shfl_xor_sync(0xffffffff, s0, o);
        s1 += __shfl_xor_sync(0xffffffff, s1, o);
        s2 += __shfl_xor_sync(0xffffffff, s2, o);
    }
    if ((t & 31) == 0) {
        atomicAdd(&cmean[b * 3 + 0], s0);
        atomicAdd(&cmean[b * 3 + 1], s1);
        atomicAdd(&cmean[b * 3 + 2], s2);
    }
}

__global__ void coord_max_p(const float* __restrict__ coords, const float* __restrict__ cmean,
                            unsigned* __restrict__ cmaxb) {
    int b = blockIdx.y;
    int n0 = blockIdx.x * 512;
    int t = threadIdx.x;
    float invn = 1.0f / (float)NP;
    float mx = cmean[b * 3 + 0] * invn, my = cmean[b * 3 + 1] * invn, mz = cmean[b * 3 + 2] * invn;
    float m = 0.0f;
    for (int n = n0 + t; n < n0 + 512; n += 256) {
        float dx = coords[(b * 3 + 0) * NP + n] - mx;
        float dy = coords[(b * 3 + 1) * NP + n] - my;
        float dz = coords[(b * 3 + 2) * NP + n] - mz;
        m = fmaxf(m, dx * dx + dy * dy + dz * dz);
    }
#pragma unroll
    for (int o = 16; o > 0; o >>= 1) m = fmaxf(m, __shfl_xor_sync(0xffffffff, m, o));
    if ((t & 31) == 0) atomicMax(&cmaxb[b], __float_as_uint(m));
}

// ---------------- voxelize scatter ----------------
__global__ void scatter(const float* __restrict__ coords, const float* __restrict__ fT,
                        const float* __restrict__ cmean, const unsigned* __restrict__ cmaxb,
                        float* __restrict__ normc, float* __restrict__ tmp,
                        float* __restrict__ cnt) {
    int t = threadIdx.x;
    int pi = blockIdx.x * 4 + (t >> 6);
    int c = t & 63;
    int b = pi / NP;
    int n = pi - b * NP;

    float invn = 1.0f / (float)NP;
    float r = sqrtf(__uint_as_float(cmaxb[b]));
    float inv = 1.0f / (2.0f * r + VOXEPS);
    float nx = (coords[(b * 3 + 0) * NP + n] - cmean[b * 3 + 0] * invn) * inv + 0.5f;
    float ny = (coords[(b * 3 + 1) * NP + n] - cmean[b * 3 + 1] * invn) * inv + 0.5f;
    float nz = (coords[(b * 3 + 2) * NP + n] - cmean[b * 3 + 2] * invn) * inv + 0.5f;
    nx = fminf(fmaxf(nx * (float)RR, 0.0f), (float)(RR - 1));
    ny = fminf(fmaxf(ny * (float)RR, 0.0f), (float)(RR - 1));
    nz = fminf(fmaxf(nz * (float)RR, 0.0f), (float)(RR - 1));
    int vx = __float2int_rn(nx), vy = __float2int_rn(ny), vz = __float2int_rn(nz);
    int v = (vx * RR + vy) * RR + vz;

    float f = fT[((size_t)b * NP + n) * CC + c];
    atomicAdd(&tmp[((size_t)b * NV + v) * CC + c], f);
    if (c == 0) atomicAdd(&cnt[b * NV + v], 1.0f);
    if (c < 3) normc[(b * 3 + c) * NP + n] = (c == 0 ? nx : (c == 1 ? ny : nz));
}

// ================= fp16 mma.sync conv (m16n8k16, baseline PTX) =============
#define LDS32(dst, addr) asm volatile("ld.shared.b32 %0, [%1];" : "=r"(dst) : "r"(addr))
#define MMA_F16(d, a0, a1, a2, a3, b0, b1)                                    \
    asm volatile(                                                             \
        "mma.sync.aligned.m16n8k16.row.col.f32.f16.f16.f32 "                  \
        "{%0,%1,%2,%3}, {%4,%5,%6,%7}, {%8,%9}, {%0,%1,%2,%3};"               \
        : "+f"(d[0]), "+f"(d[1]), "+f"(d[2]), "+f"(d[3])                      \
        : "r"(a0), "r"(a1), "r"(a2), "r"(a3), "r"(b0), "r"(b1))

#define CWF 1280          // W' u32 per buffer: 64 n-rows x 20
#define CSLAB 12240       // slab u32: 612 rows x 20
#define RES_PITCH 68
#define CONV_DYN ((2 * CWF + CSLAB) * 4)   // 59200 B

template <int INMODE>
__global__ __launch_bounds__(256, 3)
void conv3d_mma(const float* __restrict__ in, const float* __restrict__ cnt,
                float* __restrict__ out,
                const float* __restrict__ w, const float* __restrict__ bias,
                const float* __restrict__ insc, const float* __restrict__ insh,
                float* __restrict__ gsum, float* __restrict__ gsumsq) {
    extern __shared__ __align__(16) float dsm[];
    __shared__ float sc_sm[64], sh_sm[64], bias_sm[64];

    unsigned* wsm0 = (unsigned*)dsm;
    unsigned* wsm1 = (unsigned*)dsm + CWF;
    unsigned* slab = (unsigned*)dsm + 2 * CWF;
    float* res = (float*)slab;  // reused after compute (128 x 68 <= 12240)

    int b = blockIdx.z, z0 = blockIdx.y, y0 = blockIdx.x * 4;
    int t = threadIdx.x, lane = t & 31, wid = t >> 5;
    int wy = wid >> 1, wn = wid & 1;
    int gid = lane >> 2, tig = lane & 3;

    unsigned slab_s = (unsigned)__cvta_generic_to_shared(slab);
    unsigned wsm_s[2] = {(unsigned)__cvta_generic_to_shared(wsm0),
                         (unsigned)__cvta_generic_to_shared(wsm1)};

    if (t < 64) {
        bias_sm[t] = bias[t];
        if (INMODE == 2) { sc_sm[t] = insc[t]; sh_sm[t] = insh[t]; }
    }
    __syncthreads();

    float acc[2][4][4];
#pragma unroll
    for (int mt = 0; mt < 2; mt++)
#pragma unroll
        for (int nt = 0; nt < 4; nt++)
#pragma unroll
            for (int e = 0; e < 4; e++) acc[mt][nt][e] = 0.0f;

    // slab: row r = (zs*6+ys)*34+xs, 16 half2 (32 ci) per row, pitch 20 u32
    auto load_slab = [&](int cig) {
        for (int i = t; i < 4896; i += 256) {
            int zy = i / 272, r = i - zy * 272;
            int c4 = r / 34, xs = r - c4 * 34;
            int zs = zy / 6, ys = zy - zs * 6;
            int zg = z0 - 1 + zs, yg = y0 - 1 + ys, xg = xs - 1;
            bool ok = (unsigned)zg < 32u && (unsigned)yg < 32u && (unsigned)xg < 32u;
            int vox = zg * 1024 + yg * 32 + xg;
            float4 v;
            if (INMODE == 0) {
                float4 sums = ok ? __ldg((const float4*)(in + ((size_t)b * NV + vox) * CC
                                                          + cig * 32 + c4 * 4))
                                 : make_float4(0.f, 0.f, 0.f, 0.f);
                float inv = ok ? 1.0f / fmaxf(__ldg(cnt + (size_t)b * NV + vox), 1.0f) : 0.0f;
                v.x = sums.x * inv; v.y = sums.y * inv;
                v.z = sums.z * inv; v.w = sums.w * inv;
            } else {
                v = ok ? __ldg((const float4*)(in + ((size_t)b * NV + vox) * CC
                                                + cig * 32 + c4 * 4))
                       : make_float4(0.f, 0.f, 0.f, 0.f);
                int c = cig * 32 + c4 * 4;
                float u;
                u = fmaf(v.x, sc_sm[c + 0], sh_sm[c + 0]); v.x = u >= 0 ? u : ALPHA * u;
                u = fmaf(v.y, sc_sm[c + 1], sh_sm[c + 1]); v.y = u >= 0 ? u : ALPHA * u;
                u = fmaf(v.z, sc_sm[c + 2], sh_sm[c + 2]); v.z = u >= 0 ? u : ALPHA * u;
                u = fmaf(v.w, sc_sm[c + 3], sh_sm[c + 3]); v.w = u >= 0 ? u : ALPHA * u;
                if (!ok) v = make_float4(0.f, 0.f, 0.f, 0.f);  // pad AFTER transform
            }
            __half2 h0 = __floats2half2_rn(v.x, v.y);
            __half2 h1 = __floats2half2_rn(v.z, v.w);
            uint2 uu;
            uu.x = *(unsigned*)&h0;
            uu.y = *(unsigned*)&h1;
            int row = (zs * 6 + ys) * 34 + xs;
            *(uint2*)(slab + row * 20 + c4 * 2) = uu;
        }
    };

    float wlo[4], whi[4];
    auto w_prefetch = [&](int cig, int koff) {
        const float* wb = w + (size_t)(koff * 64 + cig * 32) * 64;
#pragma unroll
        for (int j = 0; j < 4; j++) {
            int e = t + j * 256;
            int k2 = e >> 6, co = e & 63;
            wlo[j] = __ldg(wb + (size_t)(2 * k2) * 64 + co);
            whi[j] = __ldg(wb + (size_t)(2 * k2 + 1) * 64 + co);
        }
    };
    auto w_sts = [&](unsigned* dst) {
#pragma unroll
        for (int j = 0; j < 4; j++) {
            int e = t + j * 256;
            int k2 = e >> 6, co = e & 63;
            __half2 h = __floats2half2_rn(wlo[j], whi[j]);
            dst[co * 20 + k2] = *(unsigned*)&h;
        }
    };

    auto compute = [&](int buf, int koff) {
        int dz = koff / 9, rem = koff - dz * 9;
        int dy = rem / 3, dx = rem - dy * 3;
        unsigned a_base = slab_s +
            (unsigned)((((dz * 6 + wy + dy) * 34) + gid + dx) * 20 + tig) * 4;
        unsigned b_base = wsm_s[buf] + (unsigned)((wn * 32 + gid) * 20 + tig) * 4;
#pragma unroll
        for (int ks = 0; ks < 2; ks++) {
            unsigned ab = a_base + ks * 32;
            unsigned bb = b_base + ks * 32;
            unsigned a0, a1, a2, a3, a4, a5, a6, a7;
            LDS32(a0, ab);            LDS32(a1, ab + 640);
            LDS32(a2, ab + 16);       LDS32(a3, ab + 656);
            LDS32(a4, ab + 1280);     LDS32(a5, ab + 1920);
            LDS32(a6, ab + 1296);     LDS32(a7, ab + 1936);
            unsigned b0[4], b1[4];
#pragma unroll
            for (int nt = 0; nt < 4; nt++) {
                LDS32(b0[nt], bb + nt * 640);
                LDS32(b1[nt], bb + nt * 640 + 16);
            }
#pragma unroll
            for (int nt = 0; nt < 4; nt++) {
                MMA_F16(acc[0][nt], a0, a1, a2, a3, b0[nt], b1[nt]);
                MMA_F16(acc[1][nt], a4, a5, a6, a7, b0[nt], b1[nt]);
            }
        }
    };

#pragma unroll 1
    for (int cig = 0; cig < 2; cig++) {
        load_slab(cig);
        w_prefetch(cig, 0);
        w_sts(wsm0);
        __syncthreads();
#pragma unroll 1
        for (int koff = 0; koff < 27; koff++) {
            if (koff < 26) w_prefetch(cig, koff + 1);
            compute(koff & 1, koff);
            if (koff < 26) w_sts((koff & 1) ? wsm0 : wsm1);
            __syncthreads();
        }
    }

    // ---- epilogue ----
#pragma unroll
    for (int mt = 0; mt < 2; mt++)
#pragma unroll
        for (int nt = 0; nt < 4; nt++) {
            int spat0 = wy * 32 + mt * 16 + gid;
            int cout0 = wn * 32 + nt * 8 + tig * 2;
            *(float2*)(res + spat0 * RES_PITCH + cout0) =
                make_float2(acc[mt][nt][0], acc[mt][nt][1]);
            *(float2*)(res + (spat0 + 8) * RES_PITCH + cout0) =
                make_float2(acc[mt][nt][2], acc[mt][nt][3]);
        }
    __syncthreads();

    {
        int s_ = t >> 1, h = t & 1;
        int vox = z0 * 1024 + (y0 + (s_ >> 5)) * 32 + (s_ & 31);
        float* op = out + ((size_t)b * NV + vox) * CC + h * 32;
        const float* rp = res + s_ * RES_PITCH + h * 32;
#pragma unroll
        for (int k = 0; k < 8; k++) {
            float4 v;
            v.x = rp[4 * k + 0] + bias_sm[h * 32 + 4 * k + 0];
            v.y = rp[4 * k + 1] + bias_sm[h * 32 + 4 * k + 1];
            v.z = rp[4 * k + 2] + bias_sm[h * 32 + 4 * k + 2];
            v.w = rp[4 * k + 3] + bias_sm[h * 32 + 4 * k + 3];
            *(float4*)(op + 4 * k) = v;
        }
    }
#pragma unroll
    for (int j = 0; j < 8; j++) {
        int c = wid * 8 + j;
        float bval = bias_sm[c];
        float s = 0, q = 0;
#pragma unroll
        for (int sy = 0; sy < 4; sy++) {
            float v = res[(sy * 32 + lane) * RES_PITCH + c] + bval;
            s += v; q += v * v;
        }
#pragma unroll
        for (int o = 16; o > 0; o >>= 1) {
            s += __shfl_xor_sync(0xffffffff, s, o);
            q += __shfl_xor_sync(0xffffffff, q, o);
        }
        if (lane == 0) { atomicAdd(&gsum[c], s); atomicAdd(&gsumsq[c], q); }
    }
}

// ================= fp16 mma.sync point GEMM + fused stats ===================
// A: fT [b][n][c] -> 128 rows x 32 half2, pitch 36 u32. B: W same packing.
// 4 k16 steps cover K=64. Banks: (36*r + tig) mod 32 = 4r+tig -> conflict-free.
#define PGA_U32 (128 * 36)   // 4608
#define PGW_U32 (64 * 36)    // 2304
#define PG_DYN ((PGA_U32 + PGW_U32) * 4 + 128 * RES_PITCH * 4)  // 62464 B

__global__ __launch_bounds__(256, 2)
void pgemm_mma(const float* __restrict__ fT, const float* __restrict__ w,
               const float* __restrict__ bias, float* __restrict__ pT,
               float* __restrict__ gsum, float* __restrict__ gsumsq) {
    extern __shared__ __align__(16) float dsm[];
    __shared__ float bias_sm[64];
    unsigned* asm0 = (unsigned*)dsm;            // [128][36]
    unsigned* wsm0 = (unsigned*)dsm + PGA_U32;  // [64][36]
    float* res = dsm;                           // reuse after compute

    int b = blockIdx.y;
    int n0 = blockIdx.x * 128;
    int t = threadIdx.x, lane = t & 31, wid = t >> 5;
    int wy = wid >> 1, wn = wid & 1;
    int gid = lane >> 2, tig = lane & 3;

    unsigned a_s = (unsigned)__cvta_generic_to_shared(asm0);
    unsigned w_s = (unsigned)__cvta_generic_to_shared(wsm0);

    if (t < 64) bias_sm[t] = bias[t];

    // stage A: 128 n-rows x 64 ch as 32 half2
    for (int i = t; i < 2048; i += 256) {      // 128 n x 16 c4
        int n = i >> 4, c4 = i & 15;
        float4 v = __ldg((const float4*)(fT + ((size_t)b * NP + n0 + n) * CC + c4 * 4));
        __half2 h0 = __floats2half2_rn(v.x, v.y);
        __half2 h1 = __floats2half2_rn(v.z, v.w);
        uint2 uu;
        uu.x = *(unsigned*)&h0;
        uu.y = *(unsigned*)&h1;
        *(uint2*)(asm0 + n * 36 + c4 * 2) = uu;
    }
    // stage W: 64 co-rows x 32 half2 (k2 = consecutive ci pairs)
    for (int i = t; i < 2048; i += 256) {      // 64 co x 32 k2
        int co = i >> 5, k2 = i & 31;
        float lo = __ldg(w + (size_t)(2 * k2) * 64 + co);
        float hi = __ldg(w + (size_t)(2 * k2 + 1) * 64 + co);
        __half2 h = __floats2half2_rn(lo, hi);
        wsm0[co * 36 + k2] = *(unsigned*)&h;
    }
    __syncthreads();

    float acc[2][4][4];
#pragma unroll
    for (int mt = 0; mt < 2; mt++)
#pragma unroll
        for (int nt = 0; nt < 4; nt++)
#pragma unroll
            for (int e = 0; e < 4; e++) acc[mt][nt][e] = 0.0f;

    unsigned a_base = a_s + (unsigned)((wy * 32 + gid) * 36 + tig) * 4;
    unsigned b_base = w_s + (unsigned)((wn * 32 + gid) * 36 + tig) * 4;
#pragma unroll
    for (int ks = 0; ks < 4; ks++) {
        unsigned ab = a_base + ks * 32;        // +8 k2 per k16 step
        unsigned bb = b_base + ks * 32;
        unsigned a0, a1, a2, a3, a4, a5, a6, a7;
        LDS32(a0, ab);            LDS32(a1, ab + 1152);   // +8 rows (8*36*4)
        LDS32(a2, ab + 16);       LDS32(a3, ab + 1168);   // k2+4
        LDS32(a4, ab + 2304);     LDS32(a5, ab + 3456);   // mtile1 (+16 rows)
        LDS32(a6, ab + 2320);     LDS32(a7, ab + 3472);
        unsigned b0[4], b1[4];
#pragma unroll
        for (int nt = 0; nt < 4; nt++) {
            LDS32(b0[nt], bb + nt * 1152);                // +8 co rows
            LDS32(b1[nt], bb + nt * 1152 + 16);
        }
#pragma unroll
        for (int nt = 0; nt < 4; nt++) {
            MMA_F16(acc[0][nt], a0, a1, a2, a3, b0[nt], b1[nt]);
            MMA_F16(acc[1][nt], a4, a5, a6, a7, b0[nt], b1[nt]);
        }
    }
    __syncthreads();   // done reading A/W smem; res aliases it

#pragma unroll
    for (int mt = 0; mt < 2; mt++)
#pragma unroll
        for (int nt = 0; nt < 4; nt++) {
            int spat0 = wy * 32 + mt * 16 + gid;
            int cout0 = wn * 32 + nt * 8 + tig * 2;
            *(float2*)(res + spat0 * RES_PITCH + cout0) =
                make_float2(acc[mt][nt][0], acc[mt][nt][1]);
            *(float2*)(res + (spat0 + 8) * RES_PITCH + cout0) =
                make_float2(acc[mt][nt][2], acc[mt][nt][3]);
        }
    __syncthreads();

    {
        int s_ = t >> 1, h = t & 1;
        float* op = pT + ((size_t)b * NP + n0 + s_) * CC + h * 32;
        const float* rp = res + s_ * RES_PITCH + h * 32;
#pragma unroll
        for (int k = 0; k < 8; k++) {
            float4 v;
            v.x = rp[4 * k + 0] + bias_sm[h * 32 + 4 * k + 0];
            v.y = rp[4 * k + 1] + bias_sm[h * 32 + 4 * k + 1];
            v.z = rp[4 * k + 2] + bias_sm[h * 32 + 4 * k + 2];
            v.w = rp[4 * k + 3] + bias_sm[h * 32 + 4 * k + 3];
            *(float4*)(op + 4 * k) = v;
        }
    }
#pragma unroll
    for (int j = 0; j < 8; j++) {
        int c = wid * 8 + j;
        float bval = bias_sm[c];
        float s = 0, q = 0;
#pragma unroll
        for (int sy = 0; sy < 4; sy++) {
            float v = res[(sy * 32 + lane) * RES_PITCH + c] + bval;
            s += v; q += v * v;
        }
#pragma unroll
        for (int o = 16; o > 0; o >>= 1) {
            s += __shfl_xor_sync(0xffffffff, s, o);
            q += __shfl_xor_sync(0xffffffff, q, o);
        }
        if (lane == 0) { atomicAdd(&gsum[c], s); atomicAdd(&gsumsq[c], q); }
    }
}

// ---------------- final: devox(BN2+lrelu on the fly) + BN(p)+lrelu + add ----
__global__ void final_k(const float* __restrict__ vT, const float* __restrict__ pT,
                        const float* __restrict__ normc,
                        const float* __restrict__ sc2, const float* __restrict__ sh2,
                        const float* __restrict__ scp, const float* __restrict__ shp,
                        float* __restrict__ out) {
    __shared__ float res[64][65];
    __shared__ int cidx[64][8];
    __shared__ float cw[64][8];
    int b = blockIdx.y;
    int n0 = blockIdx.x * 64;
    int t = threadIdx.x;

    if (t < 64) {
        int n = n0 + t;
        float xs = normc[(b * 3 + 0) * NP + n];
        float ys = normc[(b * 3 + 1) * NP + n];
        float zs = normc[(b * 3 + 2) * NP + n];
        float x0f = floorf(xs), y0f = floorf(ys), z0f = floorf(zs);
        float fx = xs - x0f, fy = ys - y0f, fz = zs - z0f;
        int x0 = (int)x0f, y0 = (int)y0f, z0 = (int)z0f;
        int x1 = min(x0 + 1, 31), y1 = min(y0 + 1, 31), z1 = min(z0 + 1, 31);
#pragma unroll
        for (int k = 0; k < 8; k++) {
            int dx = (k >> 2) & 1, dy = (k >> 1) & 1, dz = k & 1;
            float wt = (dx ? fx : 1.0f - fx) * (dy ? fy : 1.0f - fy) * (dz ? fz : 1.0f - fz);
            int idx = ((dx ? x1 : x0) * 32 + (dy ? y1 : y0)) * 32 + (dz ? z1 : z0);
            cidx[t][k] = idx;
            cw[t][k] = wt;
        }
    }
    __syncthreads();

    int c = t & 63, ty = t >> 6;
    float sc2v = sc2[c], sh2v = sh2[c];
    float scpv = scp[c], shpv = shp[c];

    for (int j = ty; j < 64; j += 4) {
        float acc = 0.0f;
#pragma unroll
        for (int k = 0; k < 8; k++) {
            float g = vT[((size_t)b * NV + cidx[j][k]) * CC + c];
            float u = fmaf(g, sc2v, sh2v);
            u = u >= 0 ? u : ALPHA * u;
            acc += cw[j][k] * u;
        }
        float pv = fmaf(pT[((size_t)b * NP + n0 + j) * CC + c], scpv, shpv);
        pv = pv >= 0 ? pv : ALPHA * pv;
        res[c][j] = acc + pv;
    }
    __syncthreads();

    for (int i = t; i < 4096; i += 256) {
        int c2 = i >> 6, j = i & 63;
        out[((size_t)b * CC + c2) * NP + n0 + j] = res[c2][j];
    }
}

// ---------------- launcher ----------------
extern "C" void kernel_launch(void* const* d_in, const int* in_sizes, int n_in,
                              void* d_out, int out_size) {
    const float* feat   = (const float*)d_in[0];
    const float* coords = (const float*)d_in[1];
    const float* c1w    = (const float*)d_in[2];
    const float* c1b    = (const float*)d_in[3];
    const float* g1     = (const float*)d_in[4];
    const float* b1     = (const float*)d_in[5];
    const float* c2w    = (const float*)d_in[6];
    const float* c2b    = (const float*)d_in[7];
    const float* g2     = (const float*)d_in[8];
    const float* b2     = (const float*)d_in[9];
    const float* pw     = (const float*)d_in[10];
    const float* pb     = (const float*)d_in[11];
    const float* pg     = (const float*)d_in[12];
    const float* pbeta  = (const float*)d_in[13];
    float* out = (float*)d_out;

    float *fT, *tmp, *cnt, *bufB, *pT, *normc, *cmean, *stats, *scsh;
    unsigned* cmaxb;
    cudaGetSymbolAddress((void**)&fT, g_fT);
    cudaGetSymbolAddress((void**)&tmp, g_tmp);
    cudaGetSymbolAddress((void**)&cnt, g_cnt);
    cudaGetSymbolAddress((void**)&bufB, g_bufB);
    cudaGetSymbolAddress((void**)&pT, g_pT);
    cudaGetSymbolAddress((void**)&normc, g_normc);
    cudaGetSymbolAddress((void**)&cmean, g_cmean);
    cudaGetSymbolAddress((void**)&cmaxb, g_cmaxb);
    cudaGetSymbolAddress((void**)&stats, g_stats);
    cudaGetSymbolAddress((void**)&scsh, g_scsh);

    float* sum1 = stats + 0 * CC;  float* sq1 = stats + 1 * CC;
    float* sum2 = stats + 2 * CC;  float* sq2 = stats + 3 * CC;
    float* psum = stats + 4 * CC;  float* psq = stats + 5 * CC;
    float* sc1 = scsh + 0 * CC;    float* sh1 = scsh + 1 * CC;
    float* sc2 = scsh + 2 * CC;    float* sh2 = scsh + 3 * CC;
    float* scp = scsh + 4 * CC;    float* shp = scsh + 5 * CC;

    cudaFuncSetAttribute(conv3d_mma<0>, cudaFuncAttributeMaxDynamicSharedMemorySize, CONV_DYN);
    cudaFuncSetAttribute(conv3d_mma<2>, cudaFuncAttributeMaxDynamicSharedMemorySize, CONV_DYN);
    cudaFuncSetAttribute(pgemm_mma, cudaFuncAttributeMaxDynamicSharedMemorySize, PG_DYN);

    const float invV = 1.0f / (float)(BB * NV);
    const float invP = 1.0f / (float)(BB * NP);

    // voxelize
    zero_kernel<<<8192, 256>>>(tmp, (size_t)BB * NV * CC);
    zero_kernel<<<256, 256>>>(cnt, (size_t)BB * NV);
    zero_small<<<1, 512>>>(stats, cmean, cmaxb);
    transpose_feat<<<dim3(NP / 32, BB), 256>>>(feat, fT);
    coord_mean_p<<<dim3(32, BB), 256>>>(coords, cmean);
    coord_max_p<<<dim3(32, BB), 256>>>(coords, cmean, cmaxb);
    scatter<<<BB * NP / 4, 256>>>(coords, fT, cmean, cmaxb, normc, tmp, cnt);

    // conv1: voxel sums+counts in (finalize fused), channels-last out
    conv3d_mma<0><<<dim3(8, 32, BB), 256, CONV_DYN>>>(tmp, cnt, bufB, c1w, c1b,
                                                      nullptr, nullptr, sum1, sq1);
    mkscale<<<1, 64>>>(sum1, sq1, g1, b1, invV, sc1, sh1);

    // conv2: channels-last in with BN1+lrelu fused, channels-last out into tmp
    conv3d_mma<2><<<dim3(8, 32, BB), 256, CONV_DYN>>>(bufB, nullptr, tmp, c2w, c2b,
                                                      sc1, sh1, sum2, sq2);
    mkscale<<<1, 64>>>(sum2, sq2, g2, b2, invV, sc2, sh2);

    // point branch: fp16 tensor-core GEMM + fused stats
    pgemm_mma<<<dim3(NP / 128, BB), 256, PG_DYN>>>(fT, pw, pb, pT, psum, psq);
    mkscale<<<1, 64>>>(psum, psq, pg, pbeta, invP, scp, shp);

    // devoxelize (BN2+lrelu applied on gather) + point BN + add
    final_k<<<dim3(NP / 64, BB), 256>>>(tmp, pT, normc, sc2, sh2, scp, shp, out);

    // coords passthrough (second tuple output), if the harness expects it
    int main_sz = BB * CC * NP;
    int coord_sz = BB * 3 * NP;
    if (out_size >= main_sz + coord_sz)
        copy_kernel<<<coord_sz / 256, 256>>>(coords, out + main_sz, coord_sz);
}

// round 14
// speedup vs baseline: 1.3902x; 1.0248x over previous
#include <cuda_runtime.h>
#include <cuda_fp16.h>

#define BB 8
#define CC 64
#define NP 16384
#define RR 32
#define NV 32768          // 32^3
#define ALPHA 0.1f
#define BNEPS 1e-4f
#define VOXEPS 1e-6f

// ---------------- scratch (device globals; no allocation allowed) ----------
__device__ float g_fT[BB * NP * CC];        // features transposed [b][n][c]
__device__ float g_tmp[BB * NV * CC];       // voxel sums [b][v][c]; later raw conv2 out
__device__ float g_cnt[BB * NV];            // voxel counts
__device__ float g_bufB[BB * CC * NV];      // conv1 output (channels-last [b][v][c])
__device__ float g_pT[BB * NP * CC];        // point branch [b][n][c]
__device__ float g_normc[BB * 3 * NP];      // normalized coords in [0,31]
__device__ float g_cmean[BB * 3];           // coordinate SUMS
__device__ unsigned g_cmaxb[BB];            // max dist^2 as float bits
__device__ float g_stats[6 * CC];           // sum1,sq1,sum2,sq2,psum,psq
__device__ float g_scsh[6 * CC];            // sc1,sh1,sc2,sh2,scp,shp

// ---------------- utility kernels ----------------
__global__ void zero_kernel(float* p, size_t n) {
    size_t i = (size_t)blockIdx.x * blockDim.x + threadIdx.x;
    size_t stride = (size_t)gridDim.x * blockDim.x;
    for (; i < n; i += stride) p[i] = 0.0f;
}

__global__ void zero_small(float* stats, float* cmean, unsigned* cmaxb) {
    int t = threadIdx.x;
    if (t < 6 * CC) stats[t] = 0.0f;
    if (t < BB * 3) cmean[t] = 0.0f;
    if (t < BB) cmaxb[t] = 0u;
}

__global__ void copy_kernel(const float* __restrict__ src, float* __restrict__ dst, int n) {
    int i = blockIdx.x * blockDim.x + threadIdx.x;
    int stride = gridDim.x * blockDim.x;
    for (; i < n; i += stride) dst[i] = src[i];
}

__global__ void mkscale(const float* __restrict__ sum, const float* __restrict__ sumsq,
                        const float* __restrict__ gamma, const float* __restrict__ beta,
                        float invcnt, float* __restrict__ sc, float* __restrict__ sh) {
    int c = threadIdx.x;
    float mean = sum[c] * invcnt;
    float var = sumsq[c] * invcnt - mean * mean;
    float s = gamma[c] * rsqrtf(var + BNEPS);
    sc[c] = s;
    sh[c] = beta[c] - mean * s;
}

// ---------------- features transpose [b][c][n] -> [b][n][c] ----------------
__global__ void transpose_feat(const float* __restrict__ feat, float* __restrict__ fT) {
    __shared__ float s[CC][33];
    int b = blockIdx.y;
    int n0 = blockIdx.x * 32;
    int t = threadIdx.x;
    for (int i = t; i < 32 * 64; i += 256) {
        int c = i >> 5, n = i & 31;
        s[c][n] = feat[(b * CC + c) * NP + n0 + n];
    }
    __syncthreads();
    for (int i = t; i < 32 * 64; i += 256) {
        int n = i >> 6, c = i & 63;
        fT[((size_t)b * NP + n0 + n) * CC + c] = s[c][n];
    }
}

// ---------------- coord statistics ----------------
__global__ void coord_mean_p(const float* __restrict__ coords, float* __restrict__ cmean) {
    int b = blockIdx.y;
    int n0 = blockIdx.x * 512;
    int t = threadIdx.x;
    float s0 = 0, s1 = 0, s2 = 0;
    for (int n = n0 + t; n < n0 + 512; n += 256) {
        s0 += coords[(b * 3 + 0) * NP + n];
        s1 += coords[(b * 3 + 1) * NP + n];
        s2 += coords[(b * 3 + 2) * NP + n];
    }
#pragma unroll
    for (int o = 16; o > 0; o >>= 1) {
        s0 += __shfl_xor_sync(0xffffffff, s0, o);
        s1 += __shfl_xor_sync(0xffffffff, s1, o);
        s2 += __shfl_xor_sync(0xffffffff, s2, o);
    }
    if ((t & 31) == 0) {
        atomicAdd(&cmean[b * 3 + 0], s0);
        atomicAdd(&cmean[b * 3 + 1], s1);
        atomicAdd(&cmean[b * 3 + 2], s2);
    }
}

__global__ void coord_max_p(const float* __restrict__ coords, const float* __restrict__ cmean,
                            unsigned* __restrict__ cmaxb) {
    int b = blockIdx.y;
    int n0 = blockIdx.x * 512;
    int t = threadIdx.x;
    float invn = 1.0f / (float)NP;
    float mx = cmean[b * 3 + 0] * invn, my = cmean[b * 3 + 1] * invn, mz = cmean[b * 3 + 2] * invn;
    float m = 0.0f;
    for (int n = n0 + t; n < n0 + 512; n += 256) {
        float dx = coords[(b * 3 + 0) * NP + n] - mx;
        float dy = coords[(b * 3 + 1) * NP + n] - my;
        float dz = coords[(b * 3 + 2) * NP + n] - mz;
        m = fmaxf(m, dx * dx + dy * dy + dz * dz);
    }
#pragma unroll
    for (int o = 16; o > 0; o >>= 1) m = fmaxf(m, __shfl_xor_sync(0xffffffff, m, o));
    if ((t & 31) == 0) atomicMax(&cmaxb[b], __float_as_uint(m));
}

// ---------------- voxelize scatter (red.v4: 16 threads/point, 4 ch each) ---
__global__ void scatter(const float* __restrict__ coords, const float* __restrict__ fT,
                        const float* __restrict__ cmean, const unsigned* __restrict__ cmaxb,
                        float* __restrict__ normc, float* __restrict__ tmp,
                        float* __restrict__ cnt) {
    int t = threadIdx.x;
    int pi = blockIdx.x * 16 + (t >> 4);
    int j = t & 15;
    int b = pi / NP;
    int n = pi - b * NP;

    float invn = 1.0f / (float)NP;
    float r = sqrtf(__uint_as_float(cmaxb[b]));
    float inv = 1.0f / (2.0f * r + VOXEPS);
    float nx = (coords[(b * 3 + 0) * NP + n] - cmean[b * 3 + 0] * invn) * inv + 0.5f;
    float ny = (coords[(b * 3 + 1) * NP + n] - cmean[b * 3 + 1] * invn) * inv + 0.5f;
    float nz = (coords[(b * 3 + 2) * NP + n] - cmean[b * 3 + 2] * invn) * inv + 0.5f;
    nx = fminf(fmaxf(nx * (float)RR, 0.0f), (float)(RR - 1));
    ny = fminf(fmaxf(ny * (float)RR, 0.0f), (float)(RR - 1));
    nz = fminf(fmaxf(nz * (float)RR, 0.0f), (float)(RR - 1));
    int vx = __float2int_rn(nx), vy = __float2int_rn(ny), vz = __float2int_rn(nz);
    int v = (vx * RR + vy) * RR + vz;

    float4 f = *(const float4*)(fT + ((size_t)b * NP + n) * CC + j * 4);
    float* dst = tmp + ((size_t)b * NV + v) * CC + j * 4;
    asm volatile("red.global.add.v4.f32 [%0], {%1,%2,%3,%4};"
                 :: "l"(dst), "f"(f.x), "f"(f.y), "f"(f.z), "f"(f.w) : "memory");
    if (j == 0) atomicAdd(&cnt[b * NV + v], 1.0f);
    if (j < 3) normc[(b * 3 + j) * NP + n] = (j == 0 ? nx : (j == 1 ? ny : nz));
}

// ================= fp16 mma.sync conv (m16n8k16, baseline PTX) =============
#define LDS32(dst, addr) asm volatile("ld.shared.b32 %0, [%1];" : "=r"(dst) : "r"(addr))
#define MMA_F16(d, a0, a1, a2, a3, b0, b1)                                    \
    asm volatile(                                                             \
        "mma.sync.aligned.m16n8k16.row.col.f32.f16.f16.f32 "                  \
        "{%0,%1,%2,%3}, {%4,%5,%6,%7}, {%8,%9}, {%0,%1,%2,%3};"               \
        : "+f"(d[0]), "+f"(d[1]), "+f"(d[2]), "+f"(d[3])                      \
        : "r"(a0), "r"(a1), "r"(a2), "r"(a3), "r"(b0), "r"(b1))

#define CWF 1280          // W' u32 per buffer: 64 n-rows x 20
#define CSLAB 12240       // slab u32: 612 rows x 20
#define RES_PITCH 68
#define CONV_DYN ((2 * CWF + CSLAB) * 4)   // 59200 B

template <int INMODE>
__global__ __launch_bounds__(256, 3)
void conv3d_mma(const float* __restrict__ in, const float* __restrict__ cnt,
                float* __restrict__ out,
                const float* __restrict__ w, const float* __restrict__ bias,
                const float* __restrict__ insc, const float* __restrict__ insh,
                float* __restrict__ gsum, float* __restrict__ gsumsq) {
    extern __shared__ __align__(16) float dsm[];
    __shared__ float sc_sm[64], sh_sm[64], bias_sm[64];

    unsigned* wsm0 = (unsigned*)dsm;
    unsigned* wsm1 = (unsigned*)dsm + CWF;
    unsigned* slab = (unsigned*)dsm + 2 * CWF;
    float* res = (float*)slab;  // reused after compute (128 x 68 <= 12240)

    int b = blockIdx.z, z0 = blockIdx.y, y0 = blockIdx.x * 4;
    int t = threadIdx.x, lane = t & 31, wid = t >> 5;
    int wy = wid >> 1, wn = wid & 1;
    int gid = lane >> 2, tig = lane & 3;

    unsigned slab_s = (unsigned)__cvta_generic_to_shared(slab);
    unsigned wsm_s[2] = {(unsigned)__cvta_generic_to_shared(wsm0),
                         (unsigned)__cvta_generic_to_shared(wsm1)};

    if (t < 64) {
        bias_sm[t] = bias[t];
        if (INMODE == 2) { sc_sm[t] = insc[t]; sh_sm[t] = insh[t]; }
    }
    __syncthreads();

    float acc[2][4][4];
#pragma unroll
    for (int mt = 0; mt < 2; mt++)
#pragma unroll
        for (int nt = 0; nt < 4; nt++)
#pragma unroll
            for (int e = 0; e < 4; e++) acc[mt][nt][e] = 0.0f;

    // slab: row r = (zs*6+ys)*34+xs, 16 half2 (32 ci) per row, pitch 20 u32
    auto load_slab = [&](int cig) {
        for (int i = t; i < 4896; i += 256) {
            int zy = i / 272, r = i - zy * 272;
            int c4 = r / 34, xs = r - c4 * 34;
            int zs = zy / 6, ys = zy - zs * 6;
            int zg = z0 - 1 + zs, yg = y0 - 1 + ys, xg = xs - 1;
            bool ok = (unsigned)zg < 32u && (unsigned)yg < 32u && (unsigned)xg < 32u;
            int vox = zg * 1024 + yg * 32 + xg;
            float4 v;
            if (INMODE == 0) {
                float4 sums = ok ? __ldg((const float4*)(in + ((size_t)b * NV + vox) * CC
                                                          + cig * 32 + c4 * 4))
                                 : make_float4(0.f, 0.f, 0.f, 0.f);
                float inv = ok ? 1.0f / fmaxf(__ldg(cnt + (size_t)b * NV + vox), 1.0f) : 0.0f;
                v.x = sums.x * inv; v.y = sums.y * inv;
                v.z = sums.z * inv; v.w = sums.w * inv;
            } else {
                v = ok ? __ldg((const float4*)(in + ((size_t)b * NV + vox) * CC
                                                + cig * 32 + c4 * 4))
                       : make_float4(0.f, 0.f, 0.f, 0.f);
                int c = cig * 32 + c4 * 4;
                float u;
                u = fmaf(v.x, sc_sm[c + 0], sh_sm[c + 0]); v.x = u >= 0 ? u : ALPHA * u;
                u = fmaf(v.y, sc_sm[c + 1], sh_sm[c + 1]); v.y = u >= 0 ? u : ALPHA * u;
                u = fmaf(v.z, sc_sm[c + 2], sh_sm[c + 2]); v.z = u >= 0 ? u : ALPHA * u;
                u = fmaf(v.w, sc_sm[c + 3], sh_sm[c + 3]); v.w = u >= 0 ? u : ALPHA * u;
                if (!ok) v = make_float4(0.f, 0.f, 0.f, 0.f);  // pad AFTER transform
            }
            __half2 h0 = __floats2half2_rn(v.x, v.y);
            __half2 h1 = __floats2half2_rn(v.z, v.w);
            uint2 uu;
            uu.x = *(unsigned*)&h0;
            uu.y = *(unsigned*)&h1;
            int row = (zs * 6 + ys) * 34 + xs;
            *(uint2*)(slab + row * 20 + c4 * 2) = uu;
        }
    };

    float wlo[4], whi[4];
    auto w_prefetch = [&](int cig, int koff) {
        const float* wb = w + (size_t)(koff * 64 + cig * 32) * 64;
#pragma unroll
        for (int j = 0; j < 4; j++) {
            int e = t + j * 256;
            int k2 = e >> 6, co = e & 63;
            wlo[j] = __ldg(wb + (size_t)(2 * k2) * 64 + co);
            whi[j] = __ldg(wb + (size_t)(2 * k2 + 1) * 64 + co);
        }
    };
    auto w_sts = [&](unsigned* dst) {
#pragma unroll
        for (int j = 0; j < 4; j++) {
            int e = t + j * 256;
            int k2 = e >> 6, co = e & 63;
            __half2 h = __floats2half2_rn(wlo[j], whi[j]);
            dst[co * 20 + k2] = *(unsigned*)&h;
        }
    };

    auto compute = [&](int buf, int koff) {
        int dz = koff / 9, rem = koff - dz * 9;
        int dy = rem / 3, dx = rem - dy * 3;
        unsigned a_base = slab_s +
            (unsigned)((((dz * 6 + wy + dy) * 34) + gid + dx) * 20 + tig) * 4;
        unsigned b_base = wsm_s[buf] + (unsigned)((wn * 32 + gid) * 20 + tig) * 4;
#pragma unroll
        for (int ks = 0; ks < 2; ks++) {
            unsigned ab = a_base + ks * 32;
            unsigned bb = b_base + ks * 32;
            unsigned a0, a1, a2, a3, a4, a5, a6, a7;
            LDS32(a0, ab);            LDS32(a1, ab + 640);
            LDS32(a2, ab + 16);       LDS32(a3, ab + 656);
            LDS32(a4, ab + 1280);     LDS32(a5, ab + 1920);
            LDS32(a6, ab + 1296);     LDS32(a7, ab + 1936);
            unsigned b0[4], b1[4];
#pragma unroll
            for (int nt = 0; nt < 4; nt++) {
                LDS32(b0[nt], bb + nt * 640);
                LDS32(b1[nt], bb + nt * 640 + 16);
            }
#pragma unroll
            for (int nt = 0; nt < 4; nt++) {
                MMA_F16(acc[0][nt], a0, a1, a2, a3, b0[nt], b1[nt]);
                MMA_F16(acc[1][nt], a4, a5, a6, a7, b0[nt], b1[nt]);
            }
        }
    };

#pragma unroll 1
    for (int cig = 0; cig < 2; cig++) {
        load_slab(cig);
        w_prefetch(cig, 0);
        w_sts(wsm0);
        __syncthreads();
#pragma unroll 1
        for (int koff = 0; koff < 27; koff++) {
            if (koff < 26) w_prefetch(cig, koff + 1);
            compute(koff & 1, koff);
            if (koff < 26) w_sts((koff & 1) ? wsm0 : wsm1);
            __syncthreads();
        }
    }

    // ---- epilogue ----
#pragma unroll
    for (int mt = 0; mt < 2; mt++)
#pragma unroll
        for (int nt = 0; nt < 4; nt++) {
            int spat0 = wy * 32 + mt * 16 + gid;
            int cout0 = wn * 32 + nt * 8 + tig * 2;
            *(float2*)(res + spat0 * RES_PITCH + cout0) =
                make_float2(acc[mt][nt][0], acc[mt][nt][1]);
            *(float2*)(res + (spat0 + 8) * RES_PITCH + cout0) =
                make_float2(acc[mt][nt][2], acc[mt][nt][3]);
        }
    __syncthreads();

    {
        int s_ = t >> 1, h = t & 1;
        int vox = z0 * 1024 + (y0 + (s_ >> 5)) * 32 + (s_ & 31);
        float* op = out + ((size_t)b * NV + vox) * CC + h * 32;
        const float* rp = res + s_ * RES_PITCH + h * 32;
#pragma unroll
        for (int k = 0; k < 8; k++) {
            float4 v;
            v.x = rp[4 * k + 0] + bias_sm[h * 32 + 4 * k + 0];
            v.y = rp[4 * k + 1] + bias_sm[h * 32 + 4 * k + 1];
            v.z = rp[4 * k + 2] + bias_sm[h * 32 + 4 * k + 2];
            v.w = rp[4 * k + 3] + bias_sm[h * 32 + 4 * k + 3];
            *(float4*)(op + 4 * k) = v;
        }
    }
#pragma unroll
    for (int j = 0; j < 8; j++) {
        int c = wid * 8 + j;
        float bval = bias_sm[c];
        float s = 0, q = 0;
#pragma unroll
        for (int sy = 0; sy < 4; sy++) {
            float v = res[(sy * 32 + lane) * RES_PITCH + c] + bval;
            s += v; q += v * v;
        }
#pragma unroll
        for (int o = 16; o > 0; o >>= 1) {
            s += __shfl_xor_sync(0xffffffff, s, o);
            q += __shfl_xor_sync(0xffffffff, q, o);
        }
        if (lane == 0) { atomicAdd(&gsum[c], s); atomicAdd(&gsumsq[c], q); }
    }
}

// ================= fp16 mma.sync point GEMM + fused stats ===================
#define PGA_U32 (128 * 36)   // 4608
#define PGW_U32 (64 * 36)    // 2304
#define PG_DYN ((PGA_U32 + PGW_U32) * 4 + 128 * RES_PITCH * 4)  // 62464 B

__global__ __launch_bounds__(256, 2)
void pgemm_mma(const float* __restrict__ fT, const float* __restrict__ w,
               const float* __restrict__ bias, float* __restrict__ pT,
               float* __restrict__ gsum, float* __restrict__ gsumsq) {
    extern __shared__ __align__(16) float dsm[];
    __shared__ float bias_sm[64];
    unsigned* asm0 = (unsigned*)dsm;            // [128][36]
    unsigned* wsm0 = (unsigned*)dsm + PGA_U32;  // [64][36]
    float* res = dsm;                           // reuse after compute

    int b = blockIdx.y;
    int n0 = blockIdx.x * 128;
    int t = threadIdx.x, lane = t & 31, wid = t >> 5;
    int wy = wid >> 1, wn = wid & 1;
    int gid = lane >> 2, tig = lane & 3;

    unsigned a_s = (unsigned)__cvta_generic_to_shared(asm0);
    unsigned w_s = (unsigned)__cvta_generic_to_shared(wsm0);

    if (t < 64) bias_sm[t] = bias[t];

    for (int i = t; i < 2048; i += 256) {      // 128 n x 16 c4
        int n = i >> 4, c4 = i & 15;
        float4 v = __ldg((const float4*)(fT + ((size_t)b * NP + n0 + n) * CC + c4 * 4));
        __half2 h0 = __floats2half2_rn(v.x, v.y);
        __half2 h1 = __floats2half2_rn(v.z, v.w);
        uint2 uu;
        uu.x = *(unsigned*)&h0;
        uu.y = *(unsigned*)&h1;
        *(uint2*)(asm0 + n * 36 + c4 * 2) = uu;
    }
    for (int i = t; i < 2048; i += 256) {      // 64 co x 32 k2
        int co = i >> 5, k2 = i & 31;
        float lo = __ldg(w + (size_t)(2 * k2) * 64 + co);
        float hi = __ldg(w + (size_t)(2 * k2 + 1) * 64 + co);
        __half2 h = __floats2half2_rn(lo, hi);
        wsm0[co * 36 + k2] = *(unsigned*)&h;
    }
    __syncthreads();

    float acc[2][4][4];
#pragma unroll
    for (int mt = 0; mt < 2; mt++)
#pragma unroll
        for (int nt = 0; nt < 4; nt++)
#pragma unroll
            for (int e = 0; e < 4; e++) acc[mt][nt][e] = 0.0f;

    unsigned a_base = a_s + (unsigned)((wy * 32 + gid) * 36 + tig) * 4;
    unsigned b_base = w_s + (unsigned)((wn * 32 + gid) * 36 + tig) * 4;
#pragma unroll
    for (int ks = 0; ks < 4; ks++) {
        unsigned ab = a_base + ks * 32;
        unsigned bb = b_base + ks * 32;
        unsigned a0, a1, a2, a3, a4, a5, a6, a7;
        LDS32(a0, ab);            LDS32(a1, ab + 1152);
        LDS32(a2, ab + 16);       LDS32(a3, ab + 1168);
        LDS32(a4, ab + 2304);     LDS32(a5, ab + 3456);
        LDS32(a6, ab + 2320);     LDS32(a7, ab + 3472);
        unsigned b0[4], b1[4];
#pragma unroll
        for (int nt = 0; nt < 4; nt++) {
            LDS32(b0[nt], bb + nt * 1152);
            LDS32(b1[nt], bb + nt * 1152 + 16);
        }
#pragma unroll
        for (int nt = 0; nt < 4; nt++) {
            MMA_F16(acc[0][nt], a0, a1, a2, a3, b0[nt], b1[nt]);
            MMA_F16(acc[1][nt], a4, a5, a6, a7, b0[nt], b1[nt]);
        }
    }
    __syncthreads();

#pragma unroll
    for (int mt = 0; mt < 2; mt++)
#pragma unroll
        for (int nt = 0; nt < 4; nt++) {
            int spat0 = wy * 32 + mt * 16 + gid;
            int cout0 = wn * 32 + nt * 8 + tig * 2;
            *(float2*)(res + spat0 * RES_PITCH + cout0) =
                make_float2(acc[mt][nt][0], acc[mt][nt][1]);
            *(float2*)(res + (spat0 + 8) * RES_PITCH + cout0) =
                make_float2(acc[mt][nt][2], acc[mt][nt][3]);
        }
    __syncthreads();

    {
        int s_ = t >> 1, h = t & 1;
        float* op = pT + ((size_t)b * NP + n0 + s_) * CC + h * 32;
        const float* rp = res + s_ * RES_PITCH + h * 32;
#pragma unroll
        for (int k = 0; k < 8; k++) {
            float4 v;
            v.x = rp[4 * k + 0] + bias_sm[h * 32 + 4 * k + 0];
            v.y = rp[4 * k + 1] + bias_sm[h * 32 + 4 * k + 1];
            v.z = rp[4 * k + 2] + bias_sm[h * 32 + 4 * k + 2];
            v.w = rp[4 * k + 3] + bias_sm[h * 32 + 4 * k + 3];
            *(float4*)(op + 4 * k) = v;
        }
    }
#pragma unroll
    for (int j = 0; j < 8; j++) {
        int c = wid * 8 + j;
        float bval = bias_sm[c];
        float s = 0, q = 0;
#pragma unroll
        for (int sy = 0; sy < 4; sy++) {
            float v = res[(sy * 32 + lane) * RES_PITCH + c] + bval;
            s += v; q += v * v;
        }
#pragma unroll
        for (int o = 16; o > 0; o >>= 1) {
            s += __shfl_xor_sync(0xffffffff, s, o);
            q += __shfl_xor_sync(0xffffffff, q, o);
        }
        if (lane == 0) { atomicAdd(&gsum[c], s); atomicAdd(&gsumsq[c], q); }
    }
}

// ---------------- final: devox(BN2+lrelu on the fly) + BN(p)+lrelu + add ----
__global__ void final_k(const float* __restrict__ vT, const float* __restrict__ pT,
                        const float* __restrict__ normc,
                        const float* __restrict__ sc2, const float* __restrict__ sh2,
                        const float* __restrict__ scp, const float* __restrict__ shp,
                        float* __restrict__ out) {
    __shared__ float res[64][65];
    __shared__ int cidx[64][8];
    __shared__ float cw[64][8];
    int b = blockIdx.y;
    int n0 = blockIdx.x * 64;
    int t = threadIdx.x;

    if (t < 64) {
        int n = n0 + t;
        float xs = normc[(b * 3 + 0) * NP + n];
        float ys = normc[(b * 3 + 1) * NP + n];
        float zs = normc[(b * 3 + 2) * NP + n];
        float x0f = floorf(xs), y0f = floorf(ys), z0f = floorf(zs);
        float fx = xs - x0f, fy = ys - y0f, fz = zs - z0f;
        int x0 = (int)x0f, y0 = (int)y0f, z0 = (int)z0f;
        int x1 = min(x0 + 1, 31), y1 = min(y0 + 1, 31), z1 = min(z0 + 1, 31);
#pragma unroll
        for (int k = 0; k < 8; k++) {
            int dx = (k >> 2) & 1, dy = (k >> 1) & 1, dz = k & 1;
            float wt = (dx ? fx : 1.0f - fx) * (dy ? fy : 1.0f - fy) * (dz ? fz : 1.0f - fz);
            int idx = ((dx ? x1 : x0) * 32 + (dy ? y1 : y0)) * 32 + (dz ? z1 : z0);
            cidx[t][k] = idx;
            cw[t][k] = wt;
        }
    }
    __syncthreads();

    int c = t & 63, ty = t >> 6;
    float sc2v = sc2[c], sh2v = sh2[c];
    float scpv = scp[c], shpv = shp[c];

    // two j's in flight per iteration (j and j+4) -> 16 outstanding gathers
    for (int j = ty; j < 64; j += 8) {
        int j2 = j + 4;
        float acc0 = 0.0f, acc1 = 0.0f;
#pragma unroll
        for (int k = 0; k < 8; k++) {
            float g0 = vT[((size_t)b * NV + cidx[j][k]) * CC + c];
            float g1 = vT[((size_t)b * NV + cidx[j2][k]) * CC + c];
            float u0 = fmaf(g0, sc2v, sh2v);
            float u1 = fmaf(g1, sc2v, sh2v);
            u0 = u0 >= 0 ? u0 : ALPHA * u0;
            u1 = u1 >= 0 ? u1 : ALPHA * u1;
            acc0 += cw[j][k] * u0;
            acc1 += cw[j2][k] * u1;
        }
        float pv0 = fmaf(pT[((size_t)b * NP + n0 + j) * CC + c], scpv, shpv);
        float pv1 = fmaf(pT[((size_t)b * NP + n0 + j2) * CC + c], scpv, shpv);
        pv0 = pv0 >= 0 ? pv0 : ALPHA * pv0;
        pv1 = pv1 >= 0 ? pv1 : ALPHA * pv1;
        res[c][j] = acc0 + pv0;
        res[c][j2] = acc1 + pv1;
    }
    __syncthreads();

    for (int i = t; i < 4096; i += 256) {
        int c2 = i >> 6, j = i & 63;
        out[((size_t)b * CC + c2) * NP + n0 + j] = res[c2][j];
    }
}

// ---------------- launcher ----------------
extern "C" void kernel_launch(void* const* d_in, const int* in_sizes, int n_in,
                              void* d_out, int out_size) {
    const float* feat   = (const float*)d_in[0];
    const float* coords = (const float*)d_in[1];
    const float* c1w    = (const float*)d_in[2];
    const float* c1b    = (const float*)d_in[3];
    const float* g1     = (const float*)d_in[4];
    const float* b1     = (const float*)d_in[5];
    const float* c2w    = (const float*)d_in[6];
    const float* c2b    = (const float*)d_in[7];
    const float* g2     = (const float*)d_in[8];
    const float* b2     = (const float*)d_in[9];
    const float* pw     = (const float*)d_in[10];
    const float* pb     = (const float*)d_in[11];
    const float* pg     = (const float*)d_in[12];
    const float* pbeta  = (const float*)d_in[13];
    float* out = (float*)d_out;

    float *fT, *tmp, *cnt, *bufB, *pT, *normc, *cmean, *stats, *scsh;
    unsigned* cmaxb;
    cudaGetSymbolAddress((void**)&fT, g_fT);
    cudaGetSymbolAddress((void**)&tmp, g_tmp);
    cudaGetSymbolAddress((void**)&cnt, g_cnt);
    cudaGetSymbolAddress((void**)&bufB, g_bufB);
    cudaGetSymbolAddress((void**)&pT, g_pT);
    cudaGetSymbolAddress((void**)&normc, g_normc);
    cudaGetSymbolAddress((void**)&cmean, g_cmean);
    cudaGetSymbolAddress((void**)&cmaxb, g_cmaxb);
    cudaGetSymbolAddress((void**)&stats, g_stats);
    cudaGetSymbolAddress((void**)&scsh, g_scsh);

    float* sum1 = stats + 0 * CC;  float* sq1 = stats + 1 * CC;
    float* sum2 = stats + 2 * CC;  float* sq2 = stats + 3 * CC;
    float* psum = stats + 4 * CC;  float* psq = stats + 5 * CC;
    float* sc1 = scsh + 0 * CC;    float* sh1 = scsh + 1 * CC;
    float* sc2 = scsh + 2 * CC;    float* sh2 = scsh + 3 * CC;
    float* scp = scsh + 4 * CC;    float* shp = scsh + 5 * CC;

    cudaFuncSetAttribute(conv3d_mma<0>, cudaFuncAttributeMaxDynamicSharedMemorySize, CONV_DYN);
    cudaFuncSetAttribute(conv3d_mma<2>, cudaFuncAttributeMaxDynamicSharedMemorySize, CONV_DYN);
    cudaFuncSetAttribute(pgemm_mma, cudaFuncAttributeMaxDynamicSharedMemorySize, PG_DYN);

    const float invV = 1.0f / (float)(BB * NV);
    const float invP = 1.0f / (float)(BB * NP);

    // voxelize
    zero_kernel<<<8192, 256>>>(tmp, (size_t)BB * NV * CC);
    zero_kernel<<<256, 256>>>(cnt, (size_t)BB * NV);
    zero_small<<<1, 512>>>(stats, cmean, cmaxb);
    transpose_feat<<<dim3(NP / 32, BB), 256>>>(feat, fT);
    coord_mean_p<<<dim3(32, BB), 256>>>(coords, cmean);
    coord_max_p<<<dim3(32, BB), 256>>>(coords, cmean, cmaxb);
    scatter<<<BB * NP / 16, 256>>>(coords, fT, cmean, cmaxb, normc, tmp, cnt);

    // conv1: voxel sums+counts in (finalize fused), channels-last out
    conv3d_mma<0><<<dim3(8, 32, BB), 256, CONV_DYN>>>(tmp, cnt, bufB, c1w, c1b,
                                                      nullptr, nullptr, sum1, sq1);
    mkscale<<<1, 64>>>(sum1, sq1, g1, b1, invV, sc1, sh1);

    // conv2: channels-last in with BN1+lrelu fused, channels-last out into tmp
    conv3d_mma<2><<<dim3(8, 32, BB), 256, CONV_DYN>>>(bufB, nullptr, tmp, c2w, c2b,
                                                      sc1, sh1, sum2, sq2);
    mkscale<<<1, 64>>>(sum2, sq2, g2, b2, invV, sc2, sh2);

    // point branch: fp16 tensor-core GEMM + fused stats
    pgemm_mma<<<dim3(NP / 128, BB), 256, PG_DYN>>>(fT, pw, pb, pT, psum, psq);
    mkscale<<<1, 64>>>(psum, psq, pg, pbeta, invP, scp, shp);

    // devoxelize (BN2+lrelu applied on gather) + point BN + add
    final_k<<<dim3(NP / 64, BB), 256>>>(tmp, pT, normc, sc2, sh2, scp, shp, out);

    // coords passthrough (second tuple output), if the harness expects it
    int main_sz = BB * CC * NP;
    int coord_sz = BB * 3 * NP;
    if (out_size >= main_sz + coord_sz)
        copy_kernel<<<coord_sz / 256, 256>>>(coords, out + main_sz, coord_sz);
}